// round 3
// baseline (speedup 1.0000x reference)
#include <cuda_runtime.h>
#include <math.h>
#include <stdint.h>

// ---------------- constants ----------------
#define BATCH 4096
#define NR 512          // routes
#define RI 4096         // routes*8
#define OD 64           // 2 caps * 32 dims
#define OUT_V_OFF 0
#define OUT_REC_OFF 262144
#define OUT_MASK_OFF 524288

// ---------------- scratch (device globals; no cudaMalloc allowed) ----------------
__device__ float g_wT[256 * 9 * 64];            // prim_w transposed [ic][k9][oc]
__device__ float g_u[(size_t)BATCH * RI];       // squashed primary caps [B][512*8]
__device__ float g_WcT[RI * OD];                // c[r,o]*W[r,o,d,i] laid out [ri][od]
__device__ float g_bij[NR * 2];
__device__ float g_c[NR * 2];
__device__ float g_s[BATCH * OD];
__device__ float g_v[BATCH * OD];
__device__ float g_G[RI * OD];
__device__ float g_h0[BATCH * 64];
__device__ float g_h1[BATCH * 512];
__device__ float g_h2[(size_t)BATCH * 1024];

// ---------------- f32x2 packed helpers (Blackwell FFMA2) ----------------
__device__ __forceinline__ uint64_t pk2(float lo, float hi) {
    uint64_t r;
    asm("mov.b64 %0, {%1, %2};" : "=l"(r) : "f"(lo), "f"(hi));
    return r;
}
__device__ __forceinline__ void upk2(uint64_t v, float& lo, float& hi) {
    asm("mov.b64 {%0, %1}, %2;" : "=f"(lo), "=f"(hi) : "l"(v));
}
__device__ __forceinline__ void ffma2(uint64_t& d, uint64_t a, uint64_t b, uint64_t c) {
    asm("fma.rn.f32x2 %0, %1, %2, %3;" : "=l"(d) : "l"(a), "l"(b), "l"(c));
}

__device__ __forceinline__ float warp_sum(float v) {
    #pragma unroll
    for (int s = 16; s > 0; s >>= 1) v += __shfl_xor_sync(0xFFFFFFFFu, v, s);
    return v;
}

// ---------------- kernel: zero buffer ----------------
__global__ void zero_kernel(float* p, int n) {
    int i = blockIdx.x * blockDim.x + threadIdx.x;
    if (i < n) p[i] = 0.0f;
}

// ---------------- kernel: transpose prim weights to [ic][k][oc] ----------------
__global__ void transpose_w_kernel(const float* __restrict__ pw) {
    int idx = blockIdx.x * blockDim.x + threadIdx.x;   // 147456
    if (idx >= 147456) return;
    int oc = idx / 2304;
    int rem = idx % 2304;
    int ic = rem / 9;
    int k = rem % 9;
    g_wT[ic * 576 + k * 64 + oc] = pw[idx];
}

// ---------------- kernel: fused conv1 + primary conv + squash ----------------
// one CTA per image, 256 threads; phase-2 inner loop uses packed f32x2 FMA,
// pairing the thread's two output rows (same weight for both lanes).
__global__ void __launch_bounds__(256, 2) conv_fused_kernel(
    const float* __restrict__ data, const float* __restrict__ w1,
    const float* __restrict__ b1, const float* __restrict__ pb)
{
    __shared__ float s_img[64];
    __shared__ float s_x[256][68];

    int b = blockIdx.x;
    int tid = threadIdx.x;

    if (tid < 64) s_img[tid] = data[b * 64 + tid];
    __syncthreads();

    // ---- phase 1: conv1 (3x3, pad 1) + relu; thread = input channel ic ----
    {
        int ic = tid;
        float w[9];
        #pragma unroll
        for (int k = 0; k < 9; k++) w[k] = w1[ic * 9 + k];
        float bias = b1[ic];
        #pragma unroll
        for (int y = 0; y < 8; y++) {
            #pragma unroll
            for (int x = 0; x < 8; x++) {
                float acc = bias;
                #pragma unroll
                for (int ky = 0; ky < 3; ky++) {
                    int iy = y + ky - 1;
                    if (iy < 0 || iy > 7) continue;
                    #pragma unroll
                    for (int kx = 0; kx < 3; kx++) {
                        int ix = x + kx - 1;
                        if (ix < 0 || ix > 7) continue;
                        acc += w[ky * 3 + kx] * s_img[iy * 8 + ix];
                    }
                }
                s_x[ic][y * 8 + x] = fmaxf(acc, 0.0f);
            }
        }
    }
    __syncthreads();

    // ---- phase 2: primary conv, packed f32x2 over the two output rows ----
    int oc = tid & 63;
    int t = tid >> 6;
    int y0 = t * 2;

    float bias = pb[oc];
    uint64_t acc[8];
    #pragma unroll
    for (int j = 0; j < 8; j++) acc[j] = pk2(bias, bias);

    for (int ic = 0; ic < 256; ic++) {
        const float* wp = g_wT + ic * 576 + oc;
        float w[9];
        #pragma unroll
        for (int k = 0; k < 9; k++) w[k] = wp[k * 64];

        #pragma unroll
        for (int ky = 0; ky < 3; ky++) {
            int r0 = y0 + ky - 1;      // in [-1, 7]
            int r1 = y0 + ky;          // in [0, 8]
            float ra[8], rb[8];
            if (r0 >= 0) {
                float4 q0 = *(const float4*)&s_x[ic][r0 * 8];
                float4 q1 = *(const float4*)&s_x[ic][r0 * 8 + 4];
                ra[0]=q0.x; ra[1]=q0.y; ra[2]=q0.z; ra[3]=q0.w;
                ra[4]=q1.x; ra[5]=q1.y; ra[6]=q1.z; ra[7]=q1.w;
            } else {
                #pragma unroll
                for (int j = 0; j < 8; j++) ra[j] = 0.0f;
            }
            if (r1 <= 7) {
                float4 q0 = *(const float4*)&s_x[ic][r1 * 8];
                float4 q1 = *(const float4*)&s_x[ic][r1 * 8 + 4];
                rb[0]=q0.x; rb[1]=q0.y; rb[2]=q0.z; rb[3]=q0.w;
                rb[4]=q1.x; rb[5]=q1.y; rb[6]=q1.z; rb[7]=q1.w;
            } else {
                #pragma unroll
                for (int j = 0; j < 8; j++) rb[j] = 0.0f;
            }
            // padded packed row: index = ix+1, ix in [-1, 8]
            uint64_t p[10];
            p[0] = 0ull; p[9] = 0ull;
            #pragma unroll
            for (int j = 0; j < 8; j++) p[j + 1] = pk2(ra[j], rb[j]);

            #pragma unroll
            for (int kx = 0; kx < 3; kx++) {
                uint64_t w2 = pk2(w[ky * 3 + kx], w[ky * 3 + kx]);
                #pragma unroll
                for (int xx = 0; xx < 8; xx++)
                    ffma2(acc[xx], p[xx + kx], w2, acc[xx]);
            }
        }
    }

    // ---- squash each 8-vector (route = oc*8 + row, dim = x) and store ----
    {
        float a0[8], a1[8];
        #pragma unroll
        for (int j = 0; j < 8; j++) upk2(acc[j], a0[j], a1[j]);
        float* base = g_u + (size_t)b * RI;
        float sq0 = 0.0f, sq1 = 0.0f;
        #pragma unroll
        for (int j = 0; j < 8; j++) { sq0 += a0[j] * a0[j]; sq1 += a1[j] * a1[j]; }
        float sc0 = sq0 / ((1.0f + sq0) * sqrtf(sq0 + 1e-9f));
        float sc1 = sq1 / ((1.0f + sq1) * sqrtf(sq1 + 1e-9f));
        float4 v0a = make_float4(a0[0]*sc0, a0[1]*sc0, a0[2]*sc0, a0[3]*sc0);
        float4 v0b = make_float4(a0[4]*sc0, a0[5]*sc0, a0[6]*sc0, a0[7]*sc0);
        float4 v1a = make_float4(a1[0]*sc1, a1[1]*sc1, a1[2]*sc1, a1[3]*sc1);
        float4 v1b = make_float4(a1[4]*sc1, a1[5]*sc1, a1[6]*sc1, a1[7]*sc1);
        float* d0 = base + (oc * 8 + y0) * 8;
        float* d1 = base + (oc * 8 + y0 + 1) * 8;
        *(float4*)(d0)     = v0a;  *(float4*)(d0 + 4) = v0b;
        *(float4*)(d1)     = v1a;  *(float4*)(d1 + 4) = v1b;
    }
}

// ---------------- kernel: softmax of b over routes (axis 0) ----------------
__global__ void softmax_routes_kernel() {
    __shared__ float red[512];
    int t = threadIdx.x;  // 512 threads
    for (int o = 0; o < 2; o++) {
        float val = g_bij[t * 2 + o];
        red[t] = val; __syncthreads();
        for (int s = 256; s > 0; s >>= 1) {
            if (t < s) red[t] = fmaxf(red[t], red[t + s]);
            __syncthreads();
        }
        float mx = red[0]; __syncthreads();
        float e = expf(val - mx);
        red[t] = e; __syncthreads();
        for (int s = 256; s > 0; s >>= 1) {
            if (t < s) red[t] += red[t + s];
            __syncthreads();
        }
        float sum = red[0]; __syncthreads();
        g_c[t * 2 + o] = e / sum;
    }
}

// ---------------- kernel: build WcT[ri][od] = c[r,o] * W[r,o,d,i] ----------------
__global__ void build_wct_kernel(const float* __restrict__ W) {
    int idx = blockIdx.x * blockDim.x + threadIdx.x;   // 262144
    if (idx >= RI * OD) return;
    int od = idx & 63, ri = idx >> 6;
    int r = ri >> 3, i = ri & 7, o = od >> 5, d = od & 31;
    g_WcT[idx] = g_c[r * 2 + o] * W[((r * 2 + o) * 32 + d) * 8 + i];
}

// ---------------- GEMM: C = act(A*B + bias);  A[MxK] rm, B[KxN] rm ----------------
__global__ void __launch_bounds__(256) gemm_ab_kernel(
    const float* __restrict__ A, const float* __restrict__ B,
    const float* __restrict__ bias, float* __restrict__ C,
    int M, int N, int K, int act)
{
    __shared__ float As[16][68];
    __shared__ float Bs[16][64];
    int tid = threadIdx.x;
    int n0 = blockIdx.x * 64, m0 = blockIdx.y * 64;
    int tx = tid & 15, ty = tid >> 4;
    uint64_t accp[4][2] = {};

    for (int k0 = 0; k0 < K; k0 += 16) {
        #pragma unroll
        for (int l = 0; l < 4; l++) {
            int lin = tid + l * 256;
            int kk = lin & 15, m = lin >> 4;
            As[kk][m] = A[(size_t)(m0 + m) * K + k0 + kk];
            int n = lin & 63, kb = lin >> 6;
            Bs[kb][n] = B[(size_t)(k0 + kb) * N + n0 + n];
        }
        __syncthreads();
        #pragma unroll
        for (int kk = 0; kk < 16; kk++) {
            float4 a = *(const float4*)&As[kk][ty * 4];
            float4 bv = *(const float4*)&Bs[kk][tx * 4];
            uint64_t pb0 = pk2(bv.x, bv.y);
            uint64_t pb1 = pk2(bv.z, bv.w);
            float av[4] = {a.x, a.y, a.z, a.w};
            #pragma unroll
            for (int i = 0; i < 4; i++) {
                uint64_t ai = pk2(av[i], av[i]);
                ffma2(accp[i][0], ai, pb0, accp[i][0]);
                ffma2(accp[i][1], ai, pb1, accp[i][1]);
            }
        }
        __syncthreads();
    }

    #pragma unroll
    for (int i = 0; i < 4; i++) {
        float acc[4];
        upk2(accp[i][0], acc[0], acc[1]);
        upk2(accp[i][1], acc[2], acc[3]);
        int m = m0 + ty * 4 + i;
        #pragma unroll
        for (int j = 0; j < 4; j++) {
            int n = n0 + tx * 4 + j;
            float v = acc[j] + (bias ? bias[n] : 0.0f);
            if (act == 1) v = fmaxf(v, 0.0f);
            else if (act == 2) v = 1.0f / (1.0f + expf(-v));
            C[(size_t)m * N + n] = v;
        }
    }
}

// ---------------- GEMM split-K (atomic): C += A*B   A[Mxlda] rm ----------------
__global__ void __launch_bounds__(256) gemm_ab_splitk_kernel(
    const float* __restrict__ A, const float* __restrict__ B, float* __restrict__ C,
    int M, int N, int lda, int Kchunk)
{
    __shared__ float As[16][68];
    __shared__ float Bs[16][64];
    int tid = threadIdx.x;
    int n0 = blockIdx.x * 64, m0 = blockIdx.y * 64;
    int kbase = blockIdx.z * Kchunk;
    int tx = tid & 15, ty = tid >> 4;
    uint64_t accp[4][2] = {};

    for (int k0 = 0; k0 < Kchunk; k0 += 16) {
        #pragma unroll
        for (int l = 0; l < 4; l++) {
            int lin = tid + l * 256;
            int kk = lin & 15, m = lin >> 4;
            As[kk][m] = A[(size_t)(m0 + m) * lda + kbase + k0 + kk];
            int n = lin & 63, kb = lin >> 6;
            Bs[kb][n] = B[(size_t)(kbase + k0 + kb) * N + n0 + n];
        }
        __syncthreads();
        #pragma unroll
        for (int kk = 0; kk < 16; kk++) {
            float4 a = *(const float4*)&As[kk][ty * 4];
            float4 bv = *(const float4*)&Bs[kk][tx * 4];
            uint64_t pb0 = pk2(bv.x, bv.y);
            uint64_t pb1 = pk2(bv.z, bv.w);
            float av[4] = {a.x, a.y, a.z, a.w};
            #pragma unroll
            for (int i = 0; i < 4; i++) {
                uint64_t ai = pk2(av[i], av[i]);
                ffma2(accp[i][0], ai, pb0, accp[i][0]);
                ffma2(accp[i][1], ai, pb1, accp[i][1]);
            }
        }
        __syncthreads();
    }
    #pragma unroll
    for (int i = 0; i < 4; i++) {
        float acc[4];
        upk2(accp[i][0], acc[0], acc[1]);
        upk2(accp[i][1], acc[2], acc[3]);
        int m = m0 + ty * 4 + i;
        #pragma unroll
        for (int j = 0; j < 4; j++) {
            int n = n0 + tx * 4 + j;
            atomicAdd(&C[(size_t)m * N + n], acc[j]);
        }
    }
}

// ---------------- GEMM split-K (atomic): C += alpha * A^T * B ; A[Ktot x M] rm --
__global__ void __launch_bounds__(256) gemm_atb_splitk_kernel(
    const float* __restrict__ A, const float* __restrict__ B, float* __restrict__ C,
    int M, int N, int Kchunk, float alpha)
{
    __shared__ float As[16][68];
    __shared__ float Bs[16][64];
    int tid = threadIdx.x;
    int n0 = blockIdx.x * 64, m0 = blockIdx.y * 64;
    int kbase = blockIdx.z * Kchunk;
    int tx = tid & 15, ty = tid >> 4;
    uint64_t accp[4][2] = {};

    for (int k0 = 0; k0 < Kchunk; k0 += 16) {
        #pragma unroll
        for (int l = 0; l < 4; l++) {
            int lin = tid + l * 256;
            int m = lin & 63, kk = lin >> 6;
            As[kk][m] = A[(size_t)(kbase + k0 + kk) * M + m0 + m];
            Bs[kk][m] = B[(size_t)(kbase + k0 + kk) * N + n0 + m];
        }
        __syncthreads();
        #pragma unroll
        for (int kk = 0; kk < 16; kk++) {
            float4 a = *(const float4*)&As[kk][ty * 4];
            float4 bv = *(const float4*)&Bs[kk][tx * 4];
            uint64_t pb0 = pk2(bv.x, bv.y);
            uint64_t pb1 = pk2(bv.z, bv.w);
            float av[4] = {a.x, a.y, a.z, a.w};
            #pragma unroll
            for (int i = 0; i < 4; i++) {
                uint64_t ai = pk2(av[i], av[i]);
                ffma2(accp[i][0], ai, pb0, accp[i][0]);
                ffma2(accp[i][1], ai, pb1, accp[i][1]);
            }
        }
        __syncthreads();
    }
    #pragma unroll
    for (int i = 0; i < 4; i++) {
        float acc[4];
        upk2(accp[i][0], acc[0], acc[1]);
        upk2(accp[i][1], acc[2], acc[3]);
        int m = m0 + ty * 4 + i;
        #pragma unroll
        for (int j = 0; j < 4; j++) {
            int n = n0 + tx * 4 + j;
            atomicAdd(&C[(size_t)m * N + n], alpha * acc[j]);
        }
    }
}

// ---------------- kernel: squash 32-vectors of s -> v ----------------
__global__ void squash_v_kernel() {
    int gid = blockIdx.x * blockDim.x + threadIdx.x;
    int warp = gid >> 5;                 // one warp per (b, o)
    int lane = gid & 31;
    if (warp >= BATCH * 2) return;
    int b = warp >> 1, o = warp & 1;
    float x = g_s[b * 64 + o * 32 + lane];
    float sq = warp_sum(x * x);
    float sc = sq / ((1.0f + sq) * sqrtf(sq + 1e-9f));
    g_v[b * 64 + o * 32 + lane] = x * sc;
}

// ---------------- kernel: b_ij update ----------------
__global__ void b_update_kernel(const float* __restrict__ W) {
    int gid = blockIdx.x * blockDim.x + threadIdx.x;
    int warp = gid >> 5;                 // one warp per (r, o), 1024 total
    int lane = gid & 31;
    if (warp >= NR * 2) return;
    int r = warp >> 1, o = warp & 1;
    float sum = 0.0f;
    for (int t = lane; t < 256; t += 32) {
        int d = t >> 3, i = t & 7;
        sum += W[(r * 2 + o) * 256 + t] * g_G[(r * 8 + i) * 64 + o * 32 + d];
    }
    sum = warp_sum(sum);
    if (lane == 0) g_bij[r * 2 + o] += sum;
}

// ---------------- kernel: mask / argmax / output write ----------------
__global__ void mask_kernel(float* __restrict__ out) {
    int gid = blockIdx.x * blockDim.x + threadIdx.x;
    int b = gid >> 5;                   // one warp per image
    int lane = gid & 31;
    if (b >= BATCH) return;
    float v0 = g_v[b * 64 + lane];
    float v1 = g_v[b * 64 + 32 + lane];
    float n0 = warp_sum(v0 * v0);
    float n1 = warp_sum(v1 * v1);
    int idx = (n1 > n0) ? 1 : 0;
    float m0 = (idx == 0) ? 1.0f : 0.0f;
    float m1 = 1.0f - m0;
    out[OUT_V_OFF + b * 64 + lane]       = v0;
    out[OUT_V_OFF + b * 64 + 32 + lane]  = v1;
    if (lane == 0) {
        out[OUT_MASK_OFF + b * 2 + 0] = m0;
        out[OUT_MASK_OFF + b * 2 + 1] = m1;
    }
    g_h0[b * 64 + lane]      = v0 * m0;
    g_h0[b * 64 + 32 + lane] = v1 * m1;
}

// ---------------- launch ----------------
extern "C" void kernel_launch(void* const* d_in, const int* in_sizes, int n_in,
                              void* d_out, int out_size)
{
    const float* data    = (const float*)d_in[0];
    const float* conv1_w = (const float*)d_in[1];
    const float* conv1_b = (const float*)d_in[2];
    const float* prim_w  = (const float*)d_in[3];
    const float* prim_b  = (const float*)d_in[4];
    const float* W_digit = (const float*)d_in[5];
    const float* dec1_w  = (const float*)d_in[6];
    const float* dec1_b  = (const float*)d_in[7];
    const float* dec2_w  = (const float*)d_in[8];
    const float* dec2_b  = (const float*)d_in[9];
    const float* dec3_w  = (const float*)d_in[10];
    const float* dec3_b  = (const float*)d_in[11];
    float* out = (float*)d_out;

    float *p_bij, *p_s, *p_G, *p_u, *p_WcT, *p_v, *p_h0, *p_h1, *p_h2;
    cudaGetSymbolAddress((void**)&p_bij, g_bij);
    cudaGetSymbolAddress((void**)&p_s,   g_s);
    cudaGetSymbolAddress((void**)&p_G,   g_G);
    cudaGetSymbolAddress((void**)&p_u,   g_u);
    cudaGetSymbolAddress((void**)&p_WcT, g_WcT);
    cudaGetSymbolAddress((void**)&p_v,   g_v);
    cudaGetSymbolAddress((void**)&p_h0,  g_h0);
    cudaGetSymbolAddress((void**)&p_h1,  g_h1);
    cudaGetSymbolAddress((void**)&p_h2,  g_h2);

    // prep (launch indices 0..4; conv lands at index 5 for ncu -s 5 -c 1)
    transpose_w_kernel<<<576, 256>>>(prim_w);                        // 0
    zero_kernel<<<4, 256>>>(p_bij, NR * 2);                          // 1
    zero_kernel<<<512, 256>>>(p_s, BATCH * 32);                      // 2 (first half)
    zero_kernel<<<512, 256>>>(p_s + BATCH * 32, BATCH * 32);         // 3 (second half)
    zero_kernel<<<1024, 256>>>(p_G, RI * 64);                        // 4

    // fused conv1 + primary caps + squash  -> g_u
    conv_fused_kernel<<<BATCH, 256>>>(data, conv1_w, conv1_b, prim_b);  // 5

    // dynamic routing, 3 iterations
    for (int it = 0; it < 3; it++) {
        softmax_routes_kernel<<<1, 512>>>();
        build_wct_kernel<<<1024, 256>>>(W_digit);
        if (it > 0) zero_kernel<<<1024, 256>>>(p_s, BATCH * 64);
        gemm_ab_splitk_kernel<<<dim3(1, 64, 4), 256>>>(p_u, p_WcT, p_s,
                                                       BATCH, 64, RI, 1024);
        squash_v_kernel<<<1024, 256>>>();
        if (it < 2) {
            if (it > 0) zero_kernel<<<1024, 256>>>(p_G, RI * 64);
            gemm_atb_splitk_kernel<<<dim3(1, 64, 8), 256>>>(p_u, p_v, p_G,
                                                            RI, 64, 512,
                                                            1.0f / (float)BATCH);
            b_update_kernel<<<128, 256>>>(W_digit);
        }
    }

    // mask + write v/masked outputs + build decoder input
    mask_kernel<<<512, 256>>>(out);

    // decoder
    gemm_ab_kernel<<<dim3(8, 64), 256>>>(p_h0, dec1_w, dec1_b, p_h1,
                                         BATCH, 512, 64, 1);
    gemm_ab_kernel<<<dim3(16, 64), 256>>>(p_h1, dec2_w, dec2_b, p_h2,
                                          BATCH, 1024, 512, 1);
    gemm_ab_kernel<<<dim3(1, 64), 256>>>(p_h2, dec3_w, dec3_b, out + OUT_REC_OFF,
                                         BATCH, 64, 1024, 2);
}

// round 4
// speedup vs baseline: 1.1868x; 1.1868x over previous
#include <cuda_runtime.h>
#include <math.h>

// ---------------- constants ----------------
#define BATCH 4096
#define NR 512          // routes
#define RI 4096         // routes*8
#define OD 64           // 2 caps * 32 dims
#define OUT_V_OFF 0
#define OUT_REC_OFF 262144
#define OUT_MASK_OFF 524288

// ---------------- scratch (device globals; no cudaMalloc allowed) ----------------
__device__ __align__(16) float g_wU[256 * 16 * 64];   // Winograd U: [ic][e16][oc]
__device__ float g_u[(size_t)BATCH * RI];              // squashed primary caps [B][512*8]
__device__ float g_WcT[RI * OD];
__device__ float g_bij[NR * 2];
__device__ float g_c[NR * 2];
__device__ float g_s[BATCH * OD];
__device__ float g_v[BATCH * OD];
__device__ float g_G[RI * OD];
__device__ float g_h0[BATCH * 64];
__device__ float g_h1[BATCH * 512];
__device__ float g_h2[(size_t)BATCH * 1024];

__device__ __forceinline__ float warp_sum(float v) {
    #pragma unroll
    for (int s = 16; s > 0; s >>= 1) v += __shfl_xor_sync(0xFFFFFFFFu, v, s);
    return v;
}

// ---------------- kernel: zero buffer ----------------
__global__ void zero_kernel(float* p, int n) {
    int i = blockIdx.x * blockDim.x + threadIdx.x;
    if (i < n) p[i] = 0.0f;
}

// ---------------- kernel: Winograd weight transform U = G g G^T ----------------
// prim_w layout [oc 64][ic 256][3][3] -> g_wU[(ic*16 + e)*64 + oc], e = i*4+l
__global__ void wu_transform_kernel(const float* __restrict__ pw) {
    int idx = blockIdx.x * blockDim.x + threadIdx.x;   // 16384
    if (idx >= 16384) return;
    int ic = idx >> 6, oc = idx & 63;
    float g[3][3];
    #pragma unroll
    for (int k = 0; k < 9; k++) g[k / 3][k % 3] = pw[oc * 2304 + ic * 9 + k];
    float a[4][3];
    #pragma unroll
    for (int j = 0; j < 3; j++) {
        a[0][j] = g[0][j];
        a[1][j] = 0.5f * (g[0][j] + g[1][j] + g[2][j]);
        a[2][j] = 0.5f * (g[0][j] - g[1][j] + g[2][j]);
        a[3][j] = g[2][j];
    }
    #pragma unroll
    for (int i = 0; i < 4; i++) {
        float u0 = a[i][0];
        float u1 = 0.5f * (a[i][0] + a[i][1] + a[i][2]);
        float u2 = 0.5f * (a[i][0] - a[i][1] + a[i][2]);
        float u3 = a[i][2];
        g_wU[(ic * 16 + i * 4 + 0) * 64 + oc] = u0;
        g_wU[(ic * 16 + i * 4 + 1) * 64 + oc] = u1;
        g_wU[(ic * 16 + i * 4 + 2) * 64 + oc] = u2;
        g_wU[(ic * 16 + i * 4 + 3) * 64 + oc] = u3;
    }
}

// ---------------- fused conv1 + Winograd primary conv + squash ----------------
// One CTA per image, 256 threads, dynamic SMEM.
// SMEM map (floats): [0,64) img | [64,16704) s_x pitch65 (reused as M 64*16*16)
//                    [16704,25920) U_s [8ic][16e][68] | [25920,28480) V_s [8ic][16e][20]
#define SM_IMG 0
#define SM_X   64
#define SM_U   16704
#define SM_V   25920
#define SM_FLOATS 28480

__global__ void __launch_bounds__(256, 1) winograd_kernel(
    const float* __restrict__ data, const float* __restrict__ w1,
    const float* __restrict__ b1, const float* __restrict__ pb)
{
    extern __shared__ float sm[];
    float* s_img = sm + SM_IMG;
    float* s_x   = sm + SM_X;     // [256][65]
    float* s_U   = sm + SM_U;     // [(icl*16+e)*68 + oc]
    float* s_V   = sm + SM_V;     // [(icl*16+e)*20 + tile]

    int b = blockIdx.x;
    int tid = threadIdx.x;

    if (tid < 64) s_img[tid] = data[b * 64 + tid];
    __syncthreads();

    // ---- phase 1: conv1 (3x3, pad 1) + relu; thread = input channel ic ----
    {
        int ic = tid;
        float w[9];
        #pragma unroll
        for (int k = 0; k < 9; k++) w[k] = w1[ic * 9 + k];
        float bias = b1[ic];
        #pragma unroll
        for (int y = 0; y < 8; y++) {
            #pragma unroll
            for (int x = 0; x < 8; x++) {
                float acc = bias;
                #pragma unroll
                for (int ky = 0; ky < 3; ky++) {
                    int iy = y + ky - 1;
                    if (iy < 0 || iy > 7) continue;
                    #pragma unroll
                    for (int kx = 0; kx < 3; kx++) {
                        int ix = x + kx - 1;
                        if (ix < 0 || ix > 7) continue;
                        acc += w[ky * 3 + kx] * s_img[iy * 8 + ix];
                    }
                }
                s_x[ic * 65 + y * 8 + x] = fmaxf(acc, 0.0f);
            }
        }
    }

    // ---- prefetch U chunk 0 into registers (32 floats/thread) ----
    float4 ubuf[8];
    {
        const float4* gw = (const float4*)g_wU;
        int base = (tid >> 1) * 16 + (tid & 1) * 8;   // row r=tid>>1, half
        #pragma unroll
        for (int q = 0; q < 8; q++) ubuf[q] = gw[base + q];
    }

    int e   = tid & 15;
    int ocg = (tid >> 4) & 7;
    int tg  = tid >> 7;          // 0 or 1
    float acc[8][8];
    #pragma unroll
    for (int j = 0; j < 8; j++)
        #pragma unroll
        for (int i = 0; i < 8; i++) acc[j][i] = 0.0f;

    for (int c = 0; c < 32; c++) {
        __syncthreads();   // prev MMA done (c=0: phase-1 done)

        // stage U regs -> SMEM (row = tid>>1, 32-float half-row)
        {
            int r = tid >> 1, half = (tid & 1) * 32;
            float4* dst = (float4*)&s_U[r * 68 + half];
            #pragma unroll
            for (int q = 0; q < 8; q++) dst[q] = ubuf[q];
        }

        // input transform: 8 ic x 16 tiles, threads 0..127
        if (tid < 128) {
            int icl = tid >> 4, tile = tid & 15;
            int ty = tile >> 2, tx = tile & 3;
            const float* xb = s_x + (c * 8 + icl) * 65;
            float d[4][4];
            #pragma unroll
            for (int k = 0; k < 4; k++) {
                int iy = 2 * ty - 1 + k;
                #pragma unroll
                for (int l = 0; l < 4; l++) {
                    int ix = 2 * tx - 1 + l;
                    d[k][l] = (iy >= 0 && iy < 8 && ix >= 0 && ix < 8)
                              ? xb[iy * 8 + ix] : 0.0f;
                }
            }
            float t[4][4];
            #pragma unroll
            for (int l = 0; l < 4; l++) {
                t[0][l] = d[0][l] - d[2][l];
                t[1][l] = d[1][l] + d[2][l];
                t[2][l] = d[2][l] - d[1][l];
                t[3][l] = d[1][l] - d[3][l];
            }
            #pragma unroll
            for (int i = 0; i < 4; i++) {
                float v0 = t[i][0] - t[i][2];
                float v1 = t[i][1] + t[i][2];
                float v2 = t[i][2] - t[i][1];
                float v3 = t[i][1] - t[i][3];
                s_V[(icl * 16 + i * 4 + 0) * 20 + tile] = v0;
                s_V[(icl * 16 + i * 4 + 1) * 20 + tile] = v1;
                s_V[(icl * 16 + i * 4 + 2) * 20 + tile] = v2;
                s_V[(icl * 16 + i * 4 + 3) * 20 + tile] = v3;
            }
        }
        __syncthreads();   // U_s/V_s ready

        // prefetch next chunk's U (latency hidden under MMA)
        if (c < 31) {
            const float4* gw = (const float4*)g_wU;
            int base = (c + 1) * 2048 + (tid >> 1) * 16 + (tid & 1) * 8;
            #pragma unroll
            for (int q = 0; q < 8; q++) ubuf[q] = gw[base + q];
        }

        // MMA: outer product, per ic: 2+2 LDS.128, 64 FFMA
        #pragma unroll
        for (int icl = 0; icl < 8; icl++) {
            int row = icl * 16 + e;
            float4 u0 = *(const float4*)&s_U[row * 68 + ocg * 8];
            float4 u1 = *(const float4*)&s_U[row * 68 + ocg * 8 + 4];
            float4 v0 = *(const float4*)&s_V[row * 20 + tg * 8];
            float4 v1 = *(const float4*)&s_V[row * 20 + tg * 8 + 4];
            float uv[8] = {u0.x, u0.y, u0.z, u0.w, u1.x, u1.y, u1.z, u1.w};
            float vv[8] = {v0.x, v0.y, v0.z, v0.w, v1.x, v1.y, v1.z, v1.w};
            #pragma unroll
            for (int j = 0; j < 8; j++)
                #pragma unroll
                for (int i = 0; i < 8; i++)
                    acc[j][i] += uv[j] * vv[i];
        }
    }
    __syncthreads();

    // stage transform-domain accumulators M[oc][tile][e] into s_x region
    {
        float* M = s_x;
        #pragma unroll
        for (int j = 0; j < 8; j++)
            #pragma unroll
            for (int i = 0; i < 8; i++)
                M[((ocg * 8 + j) * 16 + tg * 8 + i) * 16 + e] = acc[j][i];
    }
    __syncthreads();

    // output transform + bias + squash + store
    {
        const float* M = s_x;
        int oc = tid & 63, yp = tid >> 6;       // yp in 0..3, rows y=2yp,2yp+1
        float bias = pb[oc];
        float out0[8], out1[8];
        #pragma unroll
        for (int tx = 0; tx < 4; tx++) {
            const float* mp = M + (oc * 16 + yp * 4 + tx) * 16;
            float4 m0 = *(const float4*)&mp[0];
            float4 m1 = *(const float4*)&mp[4];
            float4 m2 = *(const float4*)&mp[8];
            float4 m3 = *(const float4*)&mp[12];
            float M0[4] = {m0.x, m0.y, m0.z, m0.w};
            float M1[4] = {m1.x, m1.y, m1.z, m1.w};
            float M2[4] = {m2.x, m2.y, m2.z, m2.w};
            float M3[4] = {m3.x, m3.y, m3.z, m3.w};
            float q0[4], q1[4];
            #pragma unroll
            for (int j = 0; j < 4; j++) {
                q0[j] = M0[j] + M1[j] + M2[j];
                q1[j] = M1[j] - M2[j] - M3[j];
            }
            out0[tx * 2]     = q0[0] + q0[1] + q0[2] + bias;
            out0[tx * 2 + 1] = q0[1] - q0[2] - q0[3] + bias;
            out1[tx * 2]     = q1[0] + q1[1] + q1[2] + bias;
            out1[tx * 2 + 1] = q1[1] - q1[2] - q1[3] + bias;
        }
        float sq0 = 0.0f, sq1 = 0.0f;
        #pragma unroll
        for (int j = 0; j < 8; j++) { sq0 += out0[j] * out0[j]; sq1 += out1[j] * out1[j]; }
        float sc0 = sq0 / ((1.0f + sq0) * sqrtf(sq0 + 1e-9f));
        float sc1 = sq1 / ((1.0f + sq1) * sqrtf(sq1 + 1e-9f));
        float* d0 = g_u + (size_t)b * RI + (oc * 8 + 2 * yp) * 8;
        float* d1 = d0 + 8;
        *(float4*)(d0)     = make_float4(out0[0]*sc0, out0[1]*sc0, out0[2]*sc0, out0[3]*sc0);
        *(float4*)(d0 + 4) = make_float4(out0[4]*sc0, out0[5]*sc0, out0[6]*sc0, out0[7]*sc0);
        *(float4*)(d1)     = make_float4(out1[0]*sc1, out1[1]*sc1, out1[2]*sc1, out1[3]*sc1);
        *(float4*)(d1 + 4) = make_float4(out1[4]*sc1, out1[5]*sc1, out1[6]*sc1, out1[7]*sc1);
    }
}

// ---------------- kernel: softmax of b over routes (axis 0) ----------------
__global__ void softmax_routes_kernel() {
    __shared__ float red[512];
    int t = threadIdx.x;  // 512 threads
    for (int o = 0; o < 2; o++) {
        float val = g_bij[t * 2 + o];
        red[t] = val; __syncthreads();
        for (int s = 256; s > 0; s >>= 1) {
            if (t < s) red[t] = fmaxf(red[t], red[t + s]);
            __syncthreads();
        }
        float mx = red[0]; __syncthreads();
        float e = expf(val - mx);
        red[t] = e; __syncthreads();
        for (int s = 256; s > 0; s >>= 1) {
            if (t < s) red[t] += red[t + s];
            __syncthreads();
        }
        float sum = red[0]; __syncthreads();
        g_c[t * 2 + o] = e / sum;
    }
}

// ---------------- kernel: build WcT[ri][od] = c[r,o] * W[r,o,d,i] ----------------
__global__ void build_wct_kernel(const float* __restrict__ W) {
    int idx = blockIdx.x * blockDim.x + threadIdx.x;   // 262144
    if (idx >= RI * OD) return;
    int od = idx & 63, ri = idx >> 6;
    int r = ri >> 3, i = ri & 7, o = od >> 5, d = od & 31;
    g_WcT[idx] = g_c[r * 2 + o] * W[((r * 2 + o) * 32 + d) * 8 + i];
}

// ---------------- GEMM: C = act(A*B + bias);  A[MxK] rm, B[KxN] rm ----------------
__global__ void __launch_bounds__(256) gemm_ab_kernel(
    const float* __restrict__ A, const float* __restrict__ B,
    const float* __restrict__ bias, float* __restrict__ C,
    int M, int N, int K, int act)
{
    __shared__ float As[16][68];
    __shared__ float Bs[16][64];
    int tid = threadIdx.x;
    int n0 = blockIdx.x * 64, m0 = blockIdx.y * 64;
    int tx = tid & 15, ty = tid >> 4;
    float acc[4][4] = {};

    for (int k0 = 0; k0 < K; k0 += 16) {
        #pragma unroll
        for (int l = 0; l < 4; l++) {
            int lin = tid + l * 256;
            int kk = lin & 15, m = lin >> 4;
            As[kk][m] = A[(size_t)(m0 + m) * K + k0 + kk];
            int n = lin & 63, kb = lin >> 6;
            Bs[kb][n] = B[(size_t)(k0 + kb) * N + n0 + n];
        }
        __syncthreads();
        #pragma unroll
        for (int kk = 0; kk < 16; kk++) {
            float4 a = *(const float4*)&As[kk][ty * 4];
            float4 bv = *(const float4*)&Bs[kk][tx * 4];
            float av[4] = {a.x, a.y, a.z, a.w};
            float bb[4] = {bv.x, bv.y, bv.z, bv.w};
            #pragma unroll
            for (int i = 0; i < 4; i++)
                #pragma unroll
                for (int j = 0; j < 4; j++) acc[i][j] += av[i] * bb[j];
        }
        __syncthreads();
    }

    #pragma unroll
    for (int i = 0; i < 4; i++) {
        int m = m0 + ty * 4 + i;
        #pragma unroll
        for (int j = 0; j < 4; j++) {
            int n = n0 + tx * 4 + j;
            float v = acc[i][j] + (bias ? bias[n] : 0.0f);
            if (act == 1) v = fmaxf(v, 0.0f);
            else if (act == 2) v = 1.0f / (1.0f + expf(-v));
            C[(size_t)m * N + n] = v;
        }
    }
}

// ---------------- GEMM split-K (atomic): C += A*B   A[Mxlda] rm ----------------
__global__ void __launch_bounds__(256) gemm_ab_splitk_kernel(
    const float* __restrict__ A, const float* __restrict__ B, float* __restrict__ C,
    int M, int N, int lda, int Kchunk)
{
    __shared__ float As[16][68];
    __shared__ float Bs[16][64];
    int tid = threadIdx.x;
    int n0 = blockIdx.x * 64, m0 = blockIdx.y * 64;
    int kbase = blockIdx.z * Kchunk;
    int tx = tid & 15, ty = tid >> 4;
    float acc[4][4] = {};

    for (int k0 = 0; k0 < Kchunk; k0 += 16) {
        #pragma unroll
        for (int l = 0; l < 4; l++) {
            int lin = tid + l * 256;
            int kk = lin & 15, m = lin >> 4;
            As[kk][m] = A[(size_t)(m0 + m) * lda + kbase + k0 + kk];
            int n = lin & 63, kb = lin >> 6;
            Bs[kb][n] = B[(size_t)(kbase + k0 + kb) * N + n0 + n];
        }
        __syncthreads();
        #pragma unroll
        for (int kk = 0; kk < 16; kk++) {
            float4 a = *(const float4*)&As[kk][ty * 4];
            float4 bv = *(const float4*)&Bs[kk][tx * 4];
            float av[4] = {a.x, a.y, a.z, a.w};
            float bb[4] = {bv.x, bv.y, bv.z, bv.w};
            #pragma unroll
            for (int i = 0; i < 4; i++)
                #pragma unroll
                for (int j = 0; j < 4; j++) acc[i][j] += av[i] * bb[j];
        }
        __syncthreads();
    }
    #pragma unroll
    for (int i = 0; i < 4; i++) {
        int m = m0 + ty * 4 + i;
        #pragma unroll
        for (int j = 0; j < 4; j++) {
            int n = n0 + tx * 4 + j;
            atomicAdd(&C[(size_t)m * N + n], acc[i][j]);
        }
    }
}

// ---------------- GEMM split-K (atomic): C += alpha * A^T * B ; A[Ktot x M] rm --
__global__ void __launch_bounds__(256) gemm_atb_splitk_kernel(
    const float* __restrict__ A, const float* __restrict__ B, float* __restrict__ C,
    int M, int N, int Kchunk, float alpha)
{
    __shared__ float As[16][68];
    __shared__ float Bs[16][64];
    int tid = threadIdx.x;
    int n0 = blockIdx.x * 64, m0 = blockIdx.y * 64;
    int kbase = blockIdx.z * Kchunk;
    int tx = tid & 15, ty = tid >> 4;
    float acc[4][4] = {};

    for (int k0 = 0; k0 < Kchunk; k0 += 16) {
        #pragma unroll
        for (int l = 0; l < 4; l++) {
            int lin = tid + l * 256;
            int m = lin & 63, kk = lin >> 6;
            As[kk][m] = A[(size_t)(kbase + k0 + kk) * M + m0 + m];
            Bs[kk][m] = B[(size_t)(kbase + k0 + kk) * N + n0 + m];
        }
        __syncthreads();
        #pragma unroll
        for (int kk = 0; kk < 16; kk++) {
            float4 a = *(const float4*)&As[kk][ty * 4];
            float4 bv = *(const float4*)&Bs[kk][tx * 4];
            float av[4] = {a.x, a.y, a.z, a.w};
            float bb[4] = {bv.x, bv.y, bv.z, bv.w};
            #pragma unroll
            for (int i = 0; i < 4; i++)
                #pragma unroll
                for (int j = 0; j < 4; j++) acc[i][j] += av[i] * bb[j];
        }
        __syncthreads();
    }
    #pragma unroll
    for (int i = 0; i < 4; i++) {
        int m = m0 + ty * 4 + i;
        #pragma unroll
        for (int j = 0; j < 4; j++) {
            int n = n0 + tx * 4 + j;
            atomicAdd(&C[(size_t)m * N + n], alpha * acc[i][j]);
        }
    }
}

// ---------------- kernel: squash 32-vectors of s -> v ----------------
__global__ void squash_v_kernel() {
    int gid = blockIdx.x * blockDim.x + threadIdx.x;
    int warp = gid >> 5;                 // one warp per (b, o)
    int lane = gid & 31;
    if (warp >= BATCH * 2) return;
    int b = warp >> 1, o = warp & 1;
    float x = g_s[b * 64 + o * 32 + lane];
    float sq = warp_sum(x * x);
    float sc = sq / ((1.0f + sq) * sqrtf(sq + 1e-9f));
    g_v[b * 64 + o * 32 + lane] = x * sc;
}

// ---------------- kernel: b_ij update ----------------
__global__ void b_update_kernel(const float* __restrict__ W) {
    int gid = blockIdx.x * blockDim.x + threadIdx.x;
    int warp = gid >> 5;                 // one warp per (r, o), 1024 total
    int lane = gid & 31;
    if (warp >= NR * 2) return;
    int r = warp >> 1, o = warp & 1;
    float sum = 0.0f;
    for (int t = lane; t < 256; t += 32) {
        int d = t >> 3, i = t & 7;
        sum += W[(r * 2 + o) * 256 + t] * g_G[(r * 8 + i) * 64 + o * 32 + d];
    }
    sum = warp_sum(sum);
    if (lane == 0) g_bij[r * 2 + o] += sum;
}

// ---------------- kernel: mask / argmax / output write ----------------
__global__ void mask_kernel(float* __restrict__ out) {
    int gid = blockIdx.x * blockDim.x + threadIdx.x;
    int b = gid >> 5;                   // one warp per image
    int lane = gid & 31;
    if (b >= BATCH) return;
    float v0 = g_v[b * 64 + lane];
    float v1 = g_v[b * 64 + 32 + lane];
    float n0 = warp_sum(v0 * v0);
    float n1 = warp_sum(v1 * v1);
    int idx = (n1 > n0) ? 1 : 0;
    float m0 = (idx == 0) ? 1.0f : 0.0f;
    float m1 = 1.0f - m0;
    out[OUT_V_OFF + b * 64 + lane]       = v0;
    out[OUT_V_OFF + b * 64 + 32 + lane]  = v1;
    if (lane == 0) {
        out[OUT_MASK_OFF + b * 2 + 0] = m0;
        out[OUT_MASK_OFF + b * 2 + 1] = m1;
    }
    g_h0[b * 64 + lane]      = v0 * m0;
    g_h0[b * 64 + 32 + lane] = v1 * m1;
}

// ---------------- launch ----------------
extern "C" void kernel_launch(void* const* d_in, const int* in_sizes, int n_in,
                              void* d_out, int out_size)
{
    const float* data    = (const float*)d_in[0];
    const float* conv1_w = (const float*)d_in[1];
    const float* conv1_b = (const float*)d_in[2];
    const float* prim_w  = (const float*)d_in[3];
    const float* prim_b  = (const float*)d_in[4];
    const float* W_digit = (const float*)d_in[5];
    const float* dec1_w  = (const float*)d_in[6];
    const float* dec1_b  = (const float*)d_in[7];
    const float* dec2_w  = (const float*)d_in[8];
    const float* dec2_b  = (const float*)d_in[9];
    const float* dec3_w  = (const float*)d_in[10];
    const float* dec3_b  = (const float*)d_in[11];
    float* out = (float*)d_out;

    float *p_bij, *p_s, *p_G, *p_u, *p_WcT, *p_v, *p_h0, *p_h1, *p_h2;
    cudaGetSymbolAddress((void**)&p_bij, g_bij);
    cudaGetSymbolAddress((void**)&p_s,   g_s);
    cudaGetSymbolAddress((void**)&p_G,   g_G);
    cudaGetSymbolAddress((void**)&p_u,   g_u);
    cudaGetSymbolAddress((void**)&p_WcT, g_WcT);
    cudaGetSymbolAddress((void**)&p_v,   g_v);
    cudaGetSymbolAddress((void**)&p_h0,  g_h0);
    cudaGetSymbolAddress((void**)&p_h1,  g_h1);
    cudaGetSymbolAddress((void**)&p_h2,  g_h2);

    static int smem_set = 0;
    if (!smem_set) {
        cudaFuncSetAttribute(winograd_kernel,
                             cudaFuncAttributeMaxDynamicSharedMemorySize,
                             SM_FLOATS * 4);
        smem_set = 1;
    }

    // prep (launch indices 0..4; winograd lands at index 5 for ncu -s 5 -c 1)
    wu_transform_kernel<<<64, 256>>>(prim_w);                        // 0
    zero_kernel<<<4, 256>>>(p_bij, NR * 2);                          // 1
    zero_kernel<<<512, 256>>>(p_s, BATCH * 32);                      // 2
    zero_kernel<<<512, 256>>>(p_s + BATCH * 32, BATCH * 32);         // 3
    zero_kernel<<<1024, 256>>>(p_G, RI * 64);                        // 4

    // fused conv1 + Winograd primary caps + squash -> g_u
    winograd_kernel<<<BATCH, 256, SM_FLOATS * 4>>>(data, conv1_w, conv1_b, prim_b); // 5

    // dynamic routing, 3 iterations
    for (int it = 0; it < 3; it++) {
        softmax_routes_kernel<<<1, 512>>>();
        build_wct_kernel<<<1024, 256>>>(W_digit);
        if (it > 0) zero_kernel<<<1024, 256>>>(p_s, BATCH * 64);
        gemm_ab_splitk_kernel<<<dim3(1, 64, 4), 256>>>(p_u, p_WcT, p_s,
                                                       BATCH, 64, RI, 1024);
        squash_v_kernel<<<1024, 256>>>();
        if (it < 2) {
            if (it > 0) zero_kernel<<<1024, 256>>>(p_G, RI * 64);
            gemm_atb_splitk_kernel<<<dim3(1, 64, 8), 256>>>(p_u, p_v, p_G,
                                                            RI, 64, 512,
                                                            1.0f / (float)BATCH);
            b_update_kernel<<<128, 256>>>(W_digit);
        }
    }

    // mask + write v/masked outputs + build decoder input
    mask_kernel<<<512, 256>>>(out);

    // decoder
    gemm_ab_kernel<<<dim3(8, 64), 256>>>(p_h0, dec1_w, dec1_b, p_h1,
                                         BATCH, 512, 64, 1);
    gemm_ab_kernel<<<dim3(16, 64), 256>>>(p_h1, dec2_w, dec2_b, p_h2,
                                          BATCH, 1024, 512, 1);
    gemm_ab_kernel<<<dim3(1, 64), 256>>>(p_h2, dec3_w, dec3_b, out + OUT_REC_OFF,
                                         BATCH, 64, 1024, 2);
}

// round 5
// speedup vs baseline: 2.1036x; 1.7725x over previous
#include <cuda_runtime.h>
#include <cuda_bf16.h>
#include <math.h>
#include <stdint.h>

// ---------------- constants ----------------
#define BATCH 4096
#define NR 512
#define RI 4096
#define OD 64
#define OUT_V_OFF 0
#define OUT_REC_OFF 262144
#define OUT_MASK_OFF 524288

// conv-kernel SMEM layout (bytes)
#define XROW 264                  // bf16 elems per padded-pos row (256 ic + 8 pad)
#define XT_HI 0                   // 160 * 264 * 2 = 84480
#define XT_LO 84480
#define BBUF  168960              // 2 buffers * (hi 9216 + lo 9216)
#define BPLANE 9216               // 64 rows * 144B
#define BBUFSZ 18432
#define CONV_SMEM 205824

// ---------------- scratch (device globals) ----------------
__device__ __nv_bfloat16 g_wB_hi[2304 * 64];   // [k = j*256+ic][oc]
__device__ __nv_bfloat16 g_wB_lo[2304 * 64];
__device__ float g_u[(size_t)BATCH * RI];
__device__ float g_WcT[RI * OD];
__device__ float g_bij[NR * 2];
__device__ float g_c[NR * 2];
__device__ float g_s[BATCH * OD];
__device__ float g_v[BATCH * OD];
__device__ float g_G[RI * OD];
__device__ float g_h0[BATCH * 64];
__device__ float g_h1[BATCH * 512];
__device__ float g_h2[(size_t)BATCH * 1024];

// ---------------- helpers ----------------
__device__ __forceinline__ float warp_sum(float v) {
    #pragma unroll
    for (int s = 16; s > 0; s >>= 1) v += __shfl_xor_sync(0xFFFFFFFFu, v, s);
    return v;
}
__device__ __forceinline__ float sq8(float v) {   // sum of v^2 over lanes differing in bits 2..4
    float t = v * v;
    t += __shfl_xor_sync(0xFFFFFFFFu, t, 4);
    t += __shfl_xor_sync(0xFFFFFFFFu, t, 8);
    t += __shfl_xor_sync(0xFFFFFFFFu, t, 16);
    return t;
}
__device__ __forceinline__ uint32_t smem_u32(const void* p) {
    return (uint32_t)__cvta_generic_to_shared(p);
}
__device__ __forceinline__ void ldsm_x4(uint32_t& r0, uint32_t& r1, uint32_t& r2, uint32_t& r3,
                                        uint32_t addr) {
    asm volatile("ldmatrix.sync.aligned.m8n8.x4.shared.b16 {%0,%1,%2,%3}, [%4];"
                 : "=r"(r0), "=r"(r1), "=r"(r2), "=r"(r3) : "r"(addr));
}
__device__ __forceinline__ void ldsm_x4_t(uint32_t& r0, uint32_t& r1, uint32_t& r2, uint32_t& r3,
                                          uint32_t addr) {
    asm volatile("ldmatrix.sync.aligned.m8n8.x4.trans.shared.b16 {%0,%1,%2,%3}, [%4];"
                 : "=r"(r0), "=r"(r1), "=r"(r2), "=r"(r3) : "r"(addr));
}
__device__ __forceinline__ void mma_bf16(float d[4], const uint32_t a[4],
                                         uint32_t b0, uint32_t b1) {
    asm volatile(
        "mma.sync.aligned.m16n8k16.row.col.f32.bf16.bf16.f32 "
        "{%0,%1,%2,%3}, {%4,%5,%6,%7}, {%8,%9}, {%0,%1,%2,%3};"
        : "+f"(d[0]), "+f"(d[1]), "+f"(d[2]), "+f"(d[3])
        : "r"(a[0]), "r"(a[1]), "r"(a[2]), "r"(a[3]), "r"(b0), "r"(b1));
}
__device__ __forceinline__ void cp_async16(uint32_t dst, const void* src) {
    asm volatile("cp.async.cg.shared.global [%0], [%1], 16;" :: "r"(dst), "l"(src) : "memory");
}

// ---------------- kernel: zero buffer ----------------
__global__ void zero_kernel(float* p, int n) {
    int i = blockIdx.x * blockDim.x + threadIdx.x;
    if (i < n) p[i] = 0.0f;
}

// ---------------- kernel: split prim weights into bf16 hi/lo [k][oc] ----------------
__global__ void wb_split_kernel(const float* __restrict__ pw) {
    int idx = blockIdx.x * blockDim.x + threadIdx.x;   // 147456
    if (idx >= 147456) return;
    int k = idx >> 6, oc = idx & 63;
    int j = k >> 8, ic = k & 255;
    float v = pw[oc * 2304 + ic * 9 + j];
    __nv_bfloat16 hi = __float2bfloat16(v);
    __nv_bfloat16 lo = __float2bfloat16(v - __bfloat162float(hi));
    g_wB_hi[idx] = hi;
    g_wB_lo[idx] = lo;
}

// ---------------- fused conv1 + tensor-core primary conv + squash ----------------
// one CTA per image, 256 threads (8 warps)
__global__ void __launch_bounds__(256, 1) conv_tc_kernel(
    const float* __restrict__ data, const float* __restrict__ w1,
    const float* __restrict__ b1, const float* __restrict__ pb)
{
    extern __shared__ char smem[];
    __shared__ float s_img[64];
    __nv_bfloat16* xhi = (__nv_bfloat16*)(smem + XT_HI);
    __nv_bfloat16* xlo = (__nv_bfloat16*)(smem + XT_LO);

    int b = blockIdx.x;
    int tid = threadIdx.x;
    int w = tid >> 5, lane = tid & 31;
    uint32_t sm_base = smem_u32(smem);

    // ---- prefetch weight chunk 0 (js=0, kc=0) ----
    {
        #pragma unroll
        for (int o = 0; o < 4; o++) {
            int idx = o * 256 + tid;
            int plane = idx >> 9, rem = idx & 511, r = rem >> 3, seg = rem & 7;
            const __nv_bfloat16* src = (plane ? g_wB_lo : g_wB_hi) + (size_t)r * 64 + seg * 8;
            uint32_t dst = sm_base + BBUF + plane * BPLANE + r * 144 + seg * 16;
            cp_async16(dst, src);
        }
        asm volatile("cp.async.commit_group;");
    }

    // ---- zero the padded activation planes ----
    {
        uint4 z = make_uint4(0, 0, 0, 0);
        uint4* p = (uint4*)smem;
        for (int i = tid; i < (XT_LO * 2) / 16; i += 256) p[i] = z;
    }
    if (tid < 64) s_img[tid] = data[b * 64 + tid];
    __syncthreads();

    // ---- phase 1: conv1 (3x3, pad 1) + relu; thread = input channel ic ----
    {
        int ic = tid;
        float wr[9];
        #pragma unroll
        for (int k = 0; k < 9; k++) wr[k] = w1[ic * 9 + k];
        float bias = b1[ic];
        #pragma unroll
        for (int y = 0; y < 8; y++) {
            #pragma unroll
            for (int x = 0; x < 8; x++) {
                float acc = bias;
                #pragma unroll
                for (int ky = 0; ky < 3; ky++) {
                    int iy = y + ky - 1;
                    if (iy < 0 || iy > 7) continue;
                    #pragma unroll
                    for (int kx = 0; kx < 3; kx++) {
                        int ix = x + kx - 1;
                        if (ix < 0 || ix > 7) continue;
                        acc += wr[ky * 3 + kx] * s_img[iy * 8 + ix];
                    }
                }
                acc = fmaxf(acc, 0.0f);
                __nv_bfloat16 hi = __float2bfloat16(acc);
                __nv_bfloat16 lo = __float2bfloat16(acc - __bfloat162float(hi));
                int p = (y + 1) * 16 + (x + 1);
                xhi[p * XROW + ic] = hi;
                xlo[p * XROW + ic] = lo;
            }
        }
    }

    // ---- MMA mainloop ----
    int mf = w & 3, nb = (w >> 2) * 32;
    int mloc = lane & 15, chalf = lane >> 4;
    int m = mf * 16 + mloc;
    int pbase = (m >> 3) * 16 + (m & 7);   // (y)*16 + x ; add ky*16+kx per tap

    float d[4][4];
    #pragma unroll
    for (int f = 0; f < 4; f++)
        #pragma unroll
        for (int e = 0; e < 4; e++) d[f][e] = 0.0f;

    uint32_t xhi_u = sm_base + XT_HI;
    const int lo_delta = XT_LO - XT_HI;

    for (int cid = 0; cid < 36; cid++) {
        int buf = cid & 1;
        int js = cid >> 2, kc = cid & 3;
        int ky = js / 3, kx = js - ky * 3;

        __syncthreads();   // everyone done reading buf^1 (previous chunk)

        if (cid + 1 < 36) {   // prefetch next chunk into buf^1
            int njs = (cid + 1) >> 2, nkc = (cid + 1) & 3;
            int krow0 = njs * 256 + nkc * 64;
            #pragma unroll
            for (int o = 0; o < 4; o++) {
                int idx = o * 256 + tid;
                int plane = idx >> 9, rem = idx & 511, r = rem >> 3, seg = rem & 7;
                const __nv_bfloat16* src =
                    (plane ? g_wB_lo : g_wB_hi) + (size_t)(krow0 + r) * 64 + seg * 8;
                uint32_t dst = sm_base + BBUF + (buf ^ 1) * BBUFSZ + plane * BPLANE
                               + r * 144 + seg * 16;
                cp_async16(dst, src);
            }
            asm volatile("cp.async.commit_group;");
            asm volatile("cp.async.wait_group 1;");
        } else {
            asm volatile("cp.async.wait_group 0;");
        }
        __syncthreads();   // chunk cid fully visible

        uint32_t bbase = sm_base + BBUF + buf * BBUFSZ;
        int ashift = (pbase + ky * 16 + kx) * XROW;

        #pragma unroll
        for (int k16 = 0; k16 < 4; k16++) {
            int ic0 = kc * 64 + k16 * 16;
            // A fragments (hi & lo)
            uint32_t ah[4], al[4];
            uint32_t aaddr = xhi_u + (uint32_t)(ashift + ic0 + chalf * 8) * 2u;
            ldsm_x4(ah[0], ah[1], ah[2], ah[3], aaddr);
            ldsm_x4(al[0], al[1], al[2], al[3], aaddr + lo_delta);
            // B fragments: rows k16*16 + mloc, cols nb + half*16 + chalf*8
            uint32_t bh[8], bl[8];
            uint32_t brow = bbase + (uint32_t)(k16 * 16 + mloc) * 144u;
            #pragma unroll
            for (int h = 0; h < 2; h++) {
                uint32_t baddr = brow + (uint32_t)(nb + h * 16 + chalf * 8) * 2u;
                ldsm_x4_t(bh[h*4+0], bh[h*4+1], bh[h*4+2], bh[h*4+3], baddr);
                ldsm_x4_t(bl[h*4+0], bl[h*4+1], bl[h*4+2], bl[h*4+3], baddr + BPLANE);
            }
            // 3-term split-bf16 products
            #pragma unroll
            for (int f = 0; f < 4; f++) {
                mma_bf16(d[f], ah, bh[f*2], bh[f*2+1]);
                mma_bf16(d[f], ah, bl[f*2], bl[f*2+1]);
                mma_bf16(d[f], al, bh[f*2], bh[f*2+1]);
            }
        }
    }

    // ---- epilogue: bias + squash + store u ----
    {
        int tig = lane & 3, gid = lane >> 2;   // x = gid, y = 2*mf (+1 for d2/d3)
        float* dst = g_u + (size_t)b * RI;
        #pragma unroll
        for (int f = 0; f < 4; f++) {
            int oc = nb + f * 8 + 2 * tig;
            float b0 = pb[oc], b1 = pb[oc + 1];
            float v00 = d[f][0] + b0, v01 = d[f][1] + b1;
            float v10 = d[f][2] + b0, v11 = d[f][3] + b1;
            float q00 = sq8(v00), q01 = sq8(v01), q10 = sq8(v10), q11 = sq8(v11);
            float s00 = q00 / ((1.0f + q00) * sqrtf(q00 + 1e-9f));
            float s01 = q01 / ((1.0f + q01) * sqrtf(q01 + 1e-9f));
            float s10 = q10 / ((1.0f + q10) * sqrtf(q10 + 1e-9f));
            float s11 = q11 / ((1.0f + q11) * sqrtf(q11 + 1e-9f));
            int y0 = 2 * mf;
            dst[(oc * 8 + y0) * 8 + gid]           = v00 * s00;
            dst[((oc + 1) * 8 + y0) * 8 + gid]     = v01 * s01;
            dst[(oc * 8 + y0 + 1) * 8 + gid]       = v10 * s10;
            dst[((oc + 1) * 8 + y0 + 1) * 8 + gid] = v11 * s11;
        }
    }
}

// ---------------- kernel: softmax of b over routes (axis 0) ----------------
__global__ void softmax_routes_kernel() {
    __shared__ float red[512];
    int t = threadIdx.x;
    for (int o = 0; o < 2; o++) {
        float val = g_bij[t * 2 + o];
        red[t] = val; __syncthreads();
        for (int s = 256; s > 0; s >>= 1) {
            if (t < s) red[t] = fmaxf(red[t], red[t + s]);
            __syncthreads();
        }
        float mx = red[0]; __syncthreads();
        float e = expf(val - mx);
        red[t] = e; __syncthreads();
        for (int s = 256; s > 0; s >>= 1) {
            if (t < s) red[t] += red[t + s];
            __syncthreads();
        }
        float sum = red[0]; __syncthreads();
        g_c[t * 2 + o] = e / sum;
    }
}

// ---------------- kernel: build WcT ----------------
__global__ void build_wct_kernel(const float* __restrict__ W) {
    int idx = blockIdx.x * blockDim.x + threadIdx.x;
    if (idx >= RI * OD) return;
    int od = idx & 63, ri = idx >> 6;
    int r = ri >> 3, i = ri & 7, o = od >> 5, dd = od & 31;
    g_WcT[idx] = g_c[r * 2 + o] * W[((r * 2 + o) * 32 + dd) * 8 + i];
}

// ---------------- GEMM: C = act(A*B + bias) ----------------
__global__ void __launch_bounds__(256) gemm_ab_kernel(
    const float* __restrict__ A, const float* __restrict__ B,
    const float* __restrict__ bias, float* __restrict__ C,
    int M, int N, int K, int act)
{
    __shared__ float As[16][68];
    __shared__ float Bs[16][64];
    int tid = threadIdx.x;
    int n0 = blockIdx.x * 64, m0 = blockIdx.y * 64;
    int tx = tid & 15, ty = tid >> 4;
    float acc[4][4] = {};

    for (int k0 = 0; k0 < K; k0 += 16) {
        #pragma unroll
        for (int l = 0; l < 4; l++) {
            int lin = tid + l * 256;
            int kk = lin & 15, mm = lin >> 4;
            As[kk][mm] = A[(size_t)(m0 + mm) * K + k0 + kk];
            int nn = lin & 63, kb = lin >> 6;
            Bs[kb][nn] = B[(size_t)(k0 + kb) * N + n0 + nn];
        }
        __syncthreads();
        #pragma unroll
        for (int kk = 0; kk < 16; kk++) {
            float4 a = *(const float4*)&As[kk][ty * 4];
            float4 bv = *(const float4*)&Bs[kk][tx * 4];
            float av[4] = {a.x, a.y, a.z, a.w};
            float bb[4] = {bv.x, bv.y, bv.z, bv.w};
            #pragma unroll
            for (int i = 0; i < 4; i++)
                #pragma unroll
                for (int j = 0; j < 4; j++) acc[i][j] += av[i] * bb[j];
        }
        __syncthreads();
    }
    #pragma unroll
    for (int i = 0; i < 4; i++) {
        int mm = m0 + ty * 4 + i;
        #pragma unroll
        for (int j = 0; j < 4; j++) {
            int nn = n0 + tx * 4 + j;
            float v = acc[i][j] + (bias ? bias[nn] : 0.0f);
            if (act == 1) v = fmaxf(v, 0.0f);
            else if (act == 2) v = 1.0f / (1.0f + expf(-v));
            C[(size_t)mm * N + nn] = v;
        }
    }
}

// ---------------- GEMM split-K (atomic): C += A*B ----------------
__global__ void __launch_bounds__(256) gemm_ab_splitk_kernel(
    const float* __restrict__ A, const float* __restrict__ B, float* __restrict__ C,
    int M, int N, int lda, int Kchunk)
{
    __shared__ float As[16][68];
    __shared__ float Bs[16][64];
    int tid = threadIdx.x;
    int n0 = blockIdx.x * 64, m0 = blockIdx.y * 64;
    int kbase = blockIdx.z * Kchunk;
    int tx = tid & 15, ty = tid >> 4;
    float acc[4][4] = {};

    for (int k0 = 0; k0 < Kchunk; k0 += 16) {
        #pragma unroll
        for (int l = 0; l < 4; l++) {
            int lin = tid + l * 256;
            int kk = lin & 15, mm = lin >> 4;
            As[kk][mm] = A[(size_t)(m0 + mm) * lda + kbase + k0 + kk];
            int nn = lin & 63, kb = lin >> 6;
            Bs[kb][nn] = B[(size_t)(kbase + k0 + kb) * N + n0 + nn];
        }
        __syncthreads();
        #pragma unroll
        for (int kk = 0; kk < 16; kk++) {
            float4 a = *(const float4*)&As[kk][ty * 4];
            float4 bv = *(const float4*)&Bs[kk][tx * 4];
            float av[4] = {a.x, a.y, a.z, a.w};
            float bb[4] = {bv.x, bv.y, bv.z, bv.w};
            #pragma unroll
            for (int i = 0; i < 4; i++)
                #pragma unroll
                for (int j = 0; j < 4; j++) acc[i][j] += av[i] * bb[j];
        }
        __syncthreads();
    }
    #pragma unroll
    for (int i = 0; i < 4; i++) {
        int mm = m0 + ty * 4 + i;
        #pragma unroll
        for (int j = 0; j < 4; j++) {
            int nn = n0 + tx * 4 + j;
            atomicAdd(&C[(size_t)mm * N + nn], acc[i][j]);
        }
    }
}

// ---------------- GEMM split-K (atomic): C += alpha * A^T * B ----------------
__global__ void __launch_bounds__(256) gemm_atb_splitk_kernel(
    const float* __restrict__ A, const float* __restrict__ B, float* __restrict__ C,
    int M, int N, int Kchunk, float alpha)
{
    __shared__ float As[16][68];
    __shared__ float Bs[16][64];
    int tid = threadIdx.x;
    int n0 = blockIdx.x * 64, m0 = blockIdx.y * 64;
    int kbase = blockIdx.z * Kchunk;
    int tx = tid & 15, ty = tid >> 4;
    float acc[4][4] = {};

    for (int k0 = 0; k0 < Kchunk; k0 += 16) {
        #pragma unroll
        for (int l = 0; l < 4; l++) {
            int lin = tid + l * 256;
            int mm = lin & 63, kk = lin >> 6;
            As[kk][mm] = A[(size_t)(kbase + k0 + kk) * M + m0 + mm];
            Bs[kk][mm] = B[(size_t)(kbase + k0 + kk) * N + n0 + mm];
        }
        __syncthreads();
        #pragma unroll
        for (int kk = 0; kk < 16; kk++) {
            float4 a = *(const float4*)&As[kk][ty * 4];
            float4 bv = *(const float4*)&Bs[kk][tx * 4];
            float av[4] = {a.x, a.y, a.z, a.w};
            float bb[4] = {bv.x, bv.y, bv.z, bv.w};
            #pragma unroll
            for (int i = 0; i < 4; i++)
                #pragma unroll
                for (int j = 0; j < 4; j++) acc[i][j] += av[i] * bb[j];
        }
        __syncthreads();
    }
    #pragma unroll
    for (int i = 0; i < 4; i++) {
        int mm = m0 + ty * 4 + i;
        #pragma unroll
        for (int j = 0; j < 4; j++) {
            int nn = n0 + tx * 4 + j;
            atomicAdd(&C[(size_t)mm * N + nn], alpha * acc[i][j]);
        }
    }
}

// ---------------- kernel: squash 32-vectors of s -> v ----------------
__global__ void squash_v_kernel() {
    int gid = blockIdx.x * blockDim.x + threadIdx.x;
    int warp = gid >> 5;
    int lane = gid & 31;
    if (warp >= BATCH * 2) return;
    int b = warp >> 1, o = warp & 1;
    float x = g_s[b * 64 + o * 32 + lane];
    float sq = warp_sum(x * x);
    float sc = sq / ((1.0f + sq) * sqrtf(sq + 1e-9f));
    g_v[b * 64 + o * 32 + lane] = x * sc;
}

// ---------------- kernel: b_ij update ----------------
__global__ void b_update_kernel(const float* __restrict__ W) {
    int gid = blockIdx.x * blockDim.x + threadIdx.x;
    int warp = gid >> 5;
    int lane = gid & 31;
    if (warp >= NR * 2) return;
    int r = warp >> 1, o = warp & 1;
    float sum = 0.0f;
    for (int t = lane; t < 256; t += 32) {
        int dd = t >> 3, i = t & 7;
        sum += W[(r * 2 + o) * 256 + t] * g_G[(r * 8 + i) * 64 + o * 32 + dd];
    }
    sum = warp_sum(sum);
    if (lane == 0) g_bij[r * 2 + o] += sum;
}

// ---------------- kernel: mask / argmax / output write ----------------
__global__ void mask_kernel(float* __restrict__ out) {
    int gid = blockIdx.x * blockDim.x + threadIdx.x;
    int b = gid >> 5;
    int lane = gid & 31;
    if (b >= BATCH) return;
    float v0 = g_v[b * 64 + lane];
    float v1 = g_v[b * 64 + 32 + lane];
    float n0 = warp_sum(v0 * v0);
    float n1 = warp_sum(v1 * v1);
    int idx = (n1 > n0) ? 1 : 0;
    float m0 = (idx == 0) ? 1.0f : 0.0f;
    float m1 = 1.0f - m0;
    out[OUT_V_OFF + b * 64 + lane]       = v0;
    out[OUT_V_OFF + b * 64 + 32 + lane]  = v1;
    if (lane == 0) {
        out[OUT_MASK_OFF + b * 2 + 0] = m0;
        out[OUT_MASK_OFF + b * 2 + 1] = m1;
    }
    g_h0[b * 64 + lane]      = v0 * m0;
    g_h0[b * 64 + 32 + lane] = v1 * m1;
}

// ---------------- launch ----------------
extern "C" void kernel_launch(void* const* d_in, const int* in_sizes, int n_in,
                              void* d_out, int out_size)
{
    const float* data    = (const float*)d_in[0];
    const float* conv1_w = (const float*)d_in[1];
    const float* conv1_b = (const float*)d_in[2];
    const float* prim_w  = (const float*)d_in[3];
    const float* prim_b  = (const float*)d_in[4];
    const float* W_digit = (const float*)d_in[5];
    const float* dec1_w  = (const float*)d_in[6];
    const float* dec1_b  = (const float*)d_in[7];
    const float* dec2_w  = (const float*)d_in[8];
    const float* dec2_b  = (const float*)d_in[9];
    const float* dec3_w  = (const float*)d_in[10];
    const float* dec3_b  = (const float*)d_in[11];
    float* out = (float*)d_out;

    float *p_bij, *p_s, *p_G, *p_u, *p_WcT, *p_v, *p_h0, *p_h1, *p_h2;
    cudaGetSymbolAddress((void**)&p_bij, g_bij);
    cudaGetSymbolAddress((void**)&p_s,   g_s);
    cudaGetSymbolAddress((void**)&p_G,   g_G);
    cudaGetSymbolAddress((void**)&p_u,   g_u);
    cudaGetSymbolAddress((void**)&p_WcT, g_WcT);
    cudaGetSymbolAddress((void**)&p_v,   g_v);
    cudaGetSymbolAddress((void**)&p_h0,  g_h0);
    cudaGetSymbolAddress((void**)&p_h1,  g_h1);
    cudaGetSymbolAddress((void**)&p_h2,  g_h2);

    static int smem_set = 0;
    if (!smem_set) {
        cudaFuncSetAttribute(conv_tc_kernel,
                             cudaFuncAttributeMaxDynamicSharedMemorySize, CONV_SMEM);
        smem_set = 1;
    }

    // prep (launch indices 0..4; conv_tc lands at index 5 for ncu -s 5 -c 1)
    wb_split_kernel<<<576, 256>>>(prim_w);                           // 0
    zero_kernel<<<4, 256>>>(p_bij, NR * 2);                          // 1
    zero_kernel<<<512, 256>>>(p_s, BATCH * 32);                      // 2
    zero_kernel<<<512, 256>>>(p_s + BATCH * 32, BATCH * 32);         // 3
    zero_kernel<<<1024, 256>>>(p_G, RI * 64);                        // 4

    // fused conv1 + tensor-core primary caps + squash -> g_u
    conv_tc_kernel<<<BATCH, 256, CONV_SMEM>>>(data, conv1_w, conv1_b, prim_b);  // 5

    // dynamic routing, 3 iterations
    for (int it = 0; it < 3; it++) {
        softmax_routes_kernel<<<1, 512>>>();
        build_wct_kernel<<<1024, 256>>>(W_digit);
        if (it > 0) zero_kernel<<<1024, 256>>>(p_s, BATCH * 64);
        gemm_ab_splitk_kernel<<<dim3(1, 64, 4), 256>>>(p_u, p_WcT, p_s,
                                                       BATCH, 64, RI, 1024);
        squash_v_kernel<<<1024, 256>>>();
        if (it < 2) {
            if (it > 0) zero_kernel<<<1024, 256>>>(p_G, RI * 64);
            gemm_atb_splitk_kernel<<<dim3(1, 64, 8), 256>>>(p_u, p_v, p_G,
                                                            RI, 64, 512,
                                                            1.0f / (float)BATCH);
            b_update_kernel<<<128, 256>>>(W_digit);
        }
    }

    mask_kernel<<<512, 256>>>(out);

    // decoder
    gemm_ab_kernel<<<dim3(8, 64), 256>>>(p_h0, dec1_w, dec1_b, p_h1,
                                         BATCH, 512, 64, 1);
    gemm_ab_kernel<<<dim3(16, 64), 256>>>(p_h1, dec2_w, dec2_b, p_h2,
                                          BATCH, 1024, 512, 1);
    gemm_ab_kernel<<<dim3(1, 64), 256>>>(p_h2, dec3_w, dec3_b, out + OUT_REC_OFF,
                                         BATCH, 64, 1024, 2);
}

// round 6
// speedup vs baseline: 2.2078x; 1.0495x over previous
#include <cuda_runtime.h>
#include <cuda_bf16.h>
#include <math.h>
#include <stdint.h>

// ---------------- constants ----------------
#define BATCH 4096
#define NR 512
#define RI 4096
#define OD 64
#define OUT_V_OFF 0
#define OUT_REC_OFF 262144
#define OUT_MASK_OFF 524288

// conv-kernel SMEM layout (bytes)
#define XROW 264                  // bf16 elems per padded-pos row (256 ic + 8 pad)
#define XT_HI 0                   // 160 * 264 * 2 = 84480
#define XT_LO 84480
#define BBUF  168960              // 2 buffers * (hi 9216 + lo 9216)
#define BPLANE 9216               // 64 rows * 144B
#define BBUFSZ 18432
#define CONV_SMEM 205824

// ---------------- scratch (device globals) ----------------
__device__ __nv_bfloat16 g_wB_hi[2304 * 64];   // [k = j*256+ic][oc]
__device__ __nv_bfloat16 g_wB_lo[2304 * 64];
__device__ float g_u[(size_t)BATCH * RI];
__device__ float g_WcT[RI * OD];
__device__ float g_bij[NR * 2];
__device__ float g_c[NR * 2];
__device__ float g_s[BATCH * OD];
__device__ float g_v[BATCH * OD];
__device__ float g_G[RI * OD];
__device__ float g_r[BATCH * 64];              // dec3 split-K accumulator
__device__ float g_h0[BATCH * 64];
__device__ float g_h1[BATCH * 512];
__device__ float g_h2[(size_t)BATCH * 1024];

// ---------------- helpers ----------------
__device__ __forceinline__ float warp_sum(float v) {
    #pragma unroll
    for (int s = 16; s > 0; s >>= 1) v += __shfl_xor_sync(0xFFFFFFFFu, v, s);
    return v;
}
__device__ __forceinline__ float sq8(float v) {   // sum v^2 over lanes differing in bits 2..4
    float t = v * v;
    t += __shfl_xor_sync(0xFFFFFFFFu, t, 4);
    t += __shfl_xor_sync(0xFFFFFFFFu, t, 8);
    t += __shfl_xor_sync(0xFFFFFFFFu, t, 16);
    return t;
}
__device__ __forceinline__ uint32_t smem_u32(const void* p) {
    return (uint32_t)__cvta_generic_to_shared(p);
}
__device__ __forceinline__ void ldsm_x4(uint32_t& r0, uint32_t& r1, uint32_t& r2, uint32_t& r3,
                                        uint32_t addr) {
    asm volatile("ldmatrix.sync.aligned.m8n8.x4.shared.b16 {%0,%1,%2,%3}, [%4];"
                 : "=r"(r0), "=r"(r1), "=r"(r2), "=r"(r3) : "r"(addr));
}
__device__ __forceinline__ void ldsm_x4_t(uint32_t& r0, uint32_t& r1, uint32_t& r2, uint32_t& r3,
                                          uint32_t addr) {
    asm volatile("ldmatrix.sync.aligned.m8n8.x4.trans.shared.b16 {%0,%1,%2,%3}, [%4];"
                 : "=r"(r0), "=r"(r1), "=r"(r2), "=r"(r3) : "r"(addr));
}
__device__ __forceinline__ void mma_bf16(float d[4], const uint32_t a[4],
                                         uint32_t b0, uint32_t b1) {
    asm volatile(
        "mma.sync.aligned.m16n8k16.row.col.f32.bf16.bf16.f32 "
        "{%0,%1,%2,%3}, {%4,%5,%6,%7}, {%8,%9}, {%0,%1,%2,%3};"
        : "+f"(d[0]), "+f"(d[1]), "+f"(d[2]), "+f"(d[3])
        : "r"(a[0]), "r"(a[1]), "r"(a[2]), "r"(a[3]), "r"(b0), "r"(b1));
}
__device__ __forceinline__ void cp_async16(uint32_t dst, const void* src) {
    asm volatile("cp.async.cg.shared.global [%0], [%1], 16;" :: "r"(dst), "l"(src) : "memory");
}

// ---------------- kernel: zero buffer ----------------
__global__ void zero_kernel(float* p, int n) {
    int i = blockIdx.x * blockDim.x + threadIdx.x;
    if (i < n) p[i] = 0.0f;
}

// ---------------- kernel: split prim weights into bf16 hi/lo [k][oc] ----------------
__global__ void wb_split_kernel(const float* __restrict__ pw) {
    int idx = blockIdx.x * blockDim.x + threadIdx.x;   // 147456
    if (idx >= 147456) return;
    int k = idx >> 6, oc = idx & 63;
    int j = k >> 8, ic = k & 255;
    float v = pw[oc * 2304 + ic * 9 + j];
    __nv_bfloat16 hi = __float2bfloat16(v);
    __nv_bfloat16 lo = __float2bfloat16(v - __bfloat162float(hi));
    g_wB_hi[idx] = hi;
    g_wB_lo[idx] = lo;
}

// ---------------- fused conv1 + tensor-core primary conv + squash ----------------
// one CTA per image, 512 threads (16 warps); warp = (mf = w&3) x (ng = w>>2)
__global__ void __launch_bounds__(512, 1) conv_tc_kernel(
    const float* __restrict__ data, const float* __restrict__ w1,
    const float* __restrict__ b1, const float* __restrict__ pb)
{
    extern __shared__ char smem[];
    __shared__ float s_img[64];
    __nv_bfloat16* xhi = (__nv_bfloat16*)(smem + XT_HI);
    __nv_bfloat16* xlo = (__nv_bfloat16*)(smem + XT_LO);

    int b = blockIdx.x;
    int tid = threadIdx.x;
    int w = tid >> 5, lane = tid & 31;
    uint32_t sm_base = smem_u32(smem);

    // ---- prefetch weight chunk 0 ----
    #pragma unroll
    for (int o = 0; o < 2; o++) {
        int idx = o * 512 + tid;
        int plane = idx >> 9, rem = idx & 511, r = rem >> 3, seg = rem & 7;
        const __nv_bfloat16* src = (plane ? g_wB_lo : g_wB_hi) + (size_t)r * 64 + seg * 8;
        uint32_t dst = sm_base + BBUF + plane * BPLANE + r * 144 + seg * 16;
        cp_async16(dst, src);
    }
    asm volatile("cp.async.commit_group;");

    // ---- zero the padded activation planes ----
    {
        uint4 z = make_uint4(0, 0, 0, 0);
        uint4* p = (uint4*)smem;
        for (int i = tid; i < (XT_LO * 2) / 16; i += 512) p[i] = z;
    }
    if (tid < 64) s_img[tid] = data[b * 64 + tid];
    __syncthreads();

    // ---- phase 1: conv1 (3x3, pad 1) + relu; 2 threads per ic, 4 rows each ----
    {
        int ic = tid & 255;
        int half = tid >> 8;
        float wr[9];
        #pragma unroll
        for (int k = 0; k < 9; k++) wr[k] = w1[ic * 9 + k];
        float bias = b1[ic];
        #pragma unroll
        for (int yy = 0; yy < 4; yy++) {
            int y = half * 4 + yy;
            #pragma unroll
            for (int x = 0; x < 8; x++) {
                float acc = bias;
                #pragma unroll
                for (int ky = 0; ky < 3; ky++) {
                    int iy = y + ky - 1;
                    if (iy < 0 || iy > 7) continue;
                    #pragma unroll
                    for (int kx = 0; kx < 3; kx++) {
                        int ix = x + kx - 1;
                        if (ix < 0 || ix > 7) continue;
                        acc += wr[ky * 3 + kx] * s_img[iy * 8 + ix];
                    }
                }
                acc = fmaxf(acc, 0.0f);
                __nv_bfloat16 hi = __float2bfloat16(acc);
                __nv_bfloat16 lo = __float2bfloat16(acc - __bfloat162float(hi));
                int p = (y + 1) * 16 + (x + 1);
                xhi[p * XROW + ic] = hi;
                xlo[p * XROW + ic] = lo;
            }
        }
    }
    // (first loop-iteration barrier publishes phase-1 writes)

    // ---- MMA mainloop: warp tile m16 x n16 ----
    int mf = w & 3, ng = w >> 2;
    int mloc = lane & 15, chalf = lane >> 4;
    int m = mf * 16 + mloc;
    int pbase = (m >> 3) * 16 + (m & 7);

    float d0[4] = {0.f, 0.f, 0.f, 0.f};
    float d1[4] = {0.f, 0.f, 0.f, 0.f};

    uint32_t xhi_u = sm_base + XT_HI;
    const int lo_delta = XT_LO - XT_HI;

    for (int cid = 0; cid < 36; cid++) {
        int buf = cid & 1;
        int js = cid >> 2, kc = cid & 3;
        int ky = js / 3, kx = js - ky * 3;

        asm volatile("cp.async.wait_group 0;");
        __syncthreads();   // chunk cid visible; all warps done with buf^1

        if (cid + 1 < 36) {   // prefetch next chunk into buf^1 (overlaps compute)
            int njs = (cid + 1) >> 2, nkc = (cid + 1) & 3;
            int krow0 = njs * 256 + nkc * 64;
            #pragma unroll
            for (int o = 0; o < 2; o++) {
                int idx = o * 512 + tid;
                int plane = idx >> 9, rem = idx & 511, r = rem >> 3, seg = rem & 7;
                const __nv_bfloat16* src =
                    (plane ? g_wB_lo : g_wB_hi) + (size_t)(krow0 + r) * 64 + seg * 8;
                uint32_t dst = sm_base + BBUF + (buf ^ 1) * BBUFSZ + plane * BPLANE
                               + r * 144 + seg * 16;
                cp_async16(dst, src);
            }
            asm volatile("cp.async.commit_group;");
        }

        uint32_t bbase = sm_base + BBUF + buf * BBUFSZ;
        int ashift = (pbase + ky * 16 + kx) * XROW;

        #pragma unroll
        for (int k16 = 0; k16 < 4; k16++) {
            int ic0 = kc * 64 + k16 * 16;
            uint32_t ah[4], al[4];
            uint32_t aaddr = xhi_u + (uint32_t)(ashift + ic0 + chalf * 8) * 2u;
            ldsm_x4(ah[0], ah[1], ah[2], ah[3], aaddr);
            ldsm_x4(al[0], al[1], al[2], al[3], aaddr + lo_delta);
            uint32_t bh[4], bl[4];
            uint32_t brow = bbase + (uint32_t)(k16 * 16 + mloc) * 144u;
            uint32_t baddr = brow + (uint32_t)(ng * 16 + chalf * 8) * 2u;
            ldsm_x4_t(bh[0], bh[1], bh[2], bh[3], baddr);
            ldsm_x4_t(bl[0], bl[1], bl[2], bl[3], baddr + BPLANE);
            // term-major: interleave the two accumulator chains
            mma_bf16(d0, ah, bh[0], bh[1]);
            mma_bf16(d1, ah, bh[2], bh[3]);
            mma_bf16(d0, ah, bl[0], bl[1]);
            mma_bf16(d1, ah, bl[2], bl[3]);
            mma_bf16(d0, al, bh[0], bh[1]);
            mma_bf16(d1, al, bh[2], bh[3]);
        }
    }

    // ---- epilogue: bias + squash + store u ----
    {
        int tig = lane & 3, gid = lane >> 2;   // x = gid, y = 2*mf (+1)
        float* dst = g_u + (size_t)b * RI;
        #pragma unroll
        for (int f = 0; f < 2; f++) {
            const float* d = f ? d1 : d0;
            int oc = ng * 16 + f * 8 + 2 * tig;
            float b0 = pb[oc], b1v = pb[oc + 1];
            float v00 = d[0] + b0, v01 = d[1] + b1v;
            float v10 = d[2] + b0, v11 = d[3] + b1v;
            float q00 = sq8(v00), q01 = sq8(v01), q10 = sq8(v10), q11 = sq8(v11);
            float s00 = q00 / ((1.0f + q00) * sqrtf(q00 + 1e-9f));
            float s01 = q01 / ((1.0f + q01) * sqrtf(q01 + 1e-9f));
            float s10 = q10 / ((1.0f + q10) * sqrtf(q10 + 1e-9f));
            float s11 = q11 / ((1.0f + q11) * sqrtf(q11 + 1e-9f));
            int y0 = 2 * mf;
            dst[(oc * 8 + y0) * 8 + gid]           = v00 * s00;
            dst[((oc + 1) * 8 + y0) * 8 + gid]     = v01 * s01;
            dst[(oc * 8 + y0 + 1) * 8 + gid]       = v10 * s10;
            dst[((oc + 1) * 8 + y0 + 1) * 8 + gid] = v11 * s11;
        }
    }
}

// ---------------- kernel: softmax of b over routes (axis 0) ----------------
__global__ void softmax_routes_kernel() {
    __shared__ float red[512];
    int t = threadIdx.x;
    for (int o = 0; o < 2; o++) {
        float val = g_bij[t * 2 + o];
        red[t] = val; __syncthreads();
        for (int s = 256; s > 0; s >>= 1) {
            if (t < s) red[t] = fmaxf(red[t], red[t + s]);
            __syncthreads();
        }
        float mx = red[0]; __syncthreads();
        float e = expf(val - mx);
        red[t] = e; __syncthreads();
        for (int s = 256; s > 0; s >>= 1) {
            if (t < s) red[t] += red[t + s];
            __syncthreads();
        }
        float sum = red[0]; __syncthreads();
        g_c[t * 2 + o] = e / sum;
    }
}

// ---------------- kernel: build WcT ----------------
__global__ void build_wct_kernel(const float* __restrict__ W) {
    int idx = blockIdx.x * blockDim.x + threadIdx.x;
    if (idx >= RI * OD) return;
    int od = idx & 63, ri = idx >> 6;
    int r = ri >> 3, i = ri & 7, o = od >> 5, dd = od & 31;
    g_WcT[idx] = g_c[r * 2 + o] * W[((r * 2 + o) * 32 + dd) * 8 + i];
}

// ---------------- GEMM: C = act(A*B + bias) ----------------
__global__ void __launch_bounds__(256) gemm_ab_kernel(
    const float* __restrict__ A, const float* __restrict__ B,
    const float* __restrict__ bias, float* __restrict__ C,
    int M, int N, int K, int act)
{
    __shared__ float As[16][68];
    __shared__ float Bs[16][64];
    int tid = threadIdx.x;
    int n0 = blockIdx.x * 64, m0 = blockIdx.y * 64;
    int tx = tid & 15, ty = tid >> 4;
    float acc[4][4] = {};

    for (int k0 = 0; k0 < K; k0 += 16) {
        #pragma unroll
        for (int l = 0; l < 4; l++) {
            int lin = tid + l * 256;
            int kk = lin & 15, mm = lin >> 4;
            As[kk][mm] = A[(size_t)(m0 + mm) * K + k0 + kk];
            int nn = lin & 63, kb = lin >> 6;
            Bs[kb][nn] = B[(size_t)(k0 + kb) * N + n0 + nn];
        }
        __syncthreads();
        #pragma unroll
        for (int kk = 0; kk < 16; kk++) {
            float4 a = *(const float4*)&As[kk][ty * 4];
            float4 bv = *(const float4*)&Bs[kk][tx * 4];
            float av[4] = {a.x, a.y, a.z, a.w};
            float bb[4] = {bv.x, bv.y, bv.z, bv.w};
            #pragma unroll
            for (int i = 0; i < 4; i++)
                #pragma unroll
                for (int j = 0; j < 4; j++) acc[i][j] += av[i] * bb[j];
        }
        __syncthreads();
    }
    #pragma unroll
    for (int i = 0; i < 4; i++) {
        int mm = m0 + ty * 4 + i;
        #pragma unroll
        for (int j = 0; j < 4; j++) {
            int nn = n0 + tx * 4 + j;
            float v = acc[i][j] + (bias ? bias[nn] : 0.0f);
            if (act == 1) v = fmaxf(v, 0.0f);
            else if (act == 2) v = 1.0f / (1.0f + expf(-v));
            C[(size_t)mm * N + nn] = v;
        }
    }
}

// ---------------- GEMM split-K (atomic): C += A*B ----------------
__global__ void __launch_bounds__(256) gemm_ab_splitk_kernel(
    const float* __restrict__ A, const float* __restrict__ B, float* __restrict__ C,
    int M, int N, int lda, int Kchunk)
{
    __shared__ float As[16][68];
    __shared__ float Bs[16][64];
    int tid = threadIdx.x;
    int n0 = blockIdx.x * 64, m0 = blockIdx.y * 64;
    int kbase = blockIdx.z * Kchunk;
    int tx = tid & 15, ty = tid >> 4;
    float acc[4][4] = {};

    for (int k0 = 0; k0 < Kchunk; k0 += 16) {
        #pragma unroll
        for (int l = 0; l < 4; l++) {
            int lin = tid + l * 256;
            int kk = lin & 15, mm = lin >> 4;
            As[kk][mm] = A[(size_t)(m0 + mm) * lda + kbase + k0 + kk];
            int nn = lin & 63, kb = lin >> 6;
            Bs[kb][nn] = B[(size_t)(kbase + k0 + kb) * N + n0 + nn];
        }
        __syncthreads();
        #pragma unroll
        for (int kk = 0; kk < 16; kk++) {
            float4 a = *(const float4*)&As[kk][ty * 4];
            float4 bv = *(const float4*)&Bs[kk][tx * 4];
            float av[4] = {a.x, a.y, a.z, a.w};
            float bb[4] = {bv.x, bv.y, bv.z, bv.w};
            #pragma unroll
            for (int i = 0; i < 4; i++)
                #pragma unroll
                for (int j = 0; j < 4; j++) acc[i][j] += av[i] * bb[j];
        }
        __syncthreads();
    }
    #pragma unroll
    for (int i = 0; i < 4; i++) {
        int mm = m0 + ty * 4 + i;
        #pragma unroll
        for (int j = 0; j < 4; j++) {
            int nn = n0 + tx * 4 + j;
            atomicAdd(&C[(size_t)mm * N + nn], acc[i][j]);
        }
    }
}

// ---------------- GEMM split-K (atomic): C += alpha * A^T * B ----------------
__global__ void __launch_bounds__(256) gemm_atb_splitk_kernel(
    const float* __restrict__ A, const float* __restrict__ B, float* __restrict__ C,
    int M, int N, int Kchunk, float alpha)
{
    __shared__ float As[16][68];
    __shared__ float Bs[16][64];
    int tid = threadIdx.x;
    int n0 = blockIdx.x * 64, m0 = blockIdx.y * 64;
    int kbase = blockIdx.z * Kchunk;
    int tx = tid & 15, ty = tid >> 4;
    float acc[4][4] = {};

    for (int k0 = 0; k0 < Kchunk; k0 += 16) {
        #pragma unroll
        for (int l = 0; l < 4; l++) {
            int lin = tid + l * 256;
            int mm = lin & 63, kk = lin >> 6;
            As[kk][mm] = A[(size_t)(kbase + k0 + kk) * M + m0 + mm];
            Bs[kk][mm] = B[(size_t)(kbase + k0 + kk) * N + n0 + mm];
        }
        __syncthreads();
        #pragma unroll
        for (int kk = 0; kk < 16; kk++) {
            float4 a = *(const float4*)&As[kk][ty * 4];
            float4 bv = *(const float4*)&Bs[kk][tx * 4];
            float av[4] = {a.x, a.y, a.z, a.w};
            float bb[4] = {bv.x, bv.y, bv.z, bv.w};
            #pragma unroll
            for (int i = 0; i < 4; i++)
                #pragma unroll
                for (int j = 0; j < 4; j++) acc[i][j] += av[i] * bb[j];
        }
        __syncthreads();
    }
    #pragma unroll
    for (int i = 0; i < 4; i++) {
        int mm = m0 + ty * 4 + i;
        #pragma unroll
        for (int j = 0; j < 4; j++) {
            int nn = n0 + tx * 4 + j;
            atomicAdd(&C[(size_t)mm * N + nn], alpha * acc[i][j]);
        }
    }
}

// ---------------- kernel: squash 32-vectors of s -> v ----------------
__global__ void squash_v_kernel() {
    int gid = blockIdx.x * blockDim.x + threadIdx.x;
    int warp = gid >> 5;
    int lane = gid & 31;
    if (warp >= BATCH * 2) return;
    int b = warp >> 1, o = warp & 1;
    float x = g_s[b * 64 + o * 32 + lane];
    float sq = warp_sum(x * x);
    float sc = sq / ((1.0f + sq) * sqrtf(sq + 1e-9f));
    g_v[b * 64 + o * 32 + lane] = x * sc;
}

// ---------------- kernel: b_ij update ----------------
__global__ void b_update_kernel(const float* __restrict__ W) {
    int gid = blockIdx.x * blockDim.x + threadIdx.x;
    int warp = gid >> 5;
    int lane = gid & 31;
    if (warp >= NR * 2) return;
    int r = warp >> 1, o = warp & 1;
    float sum = 0.0f;
    for (int t = lane; t < 256; t += 32) {
        int dd = t >> 3, i = t & 7;
        sum += W[(r * 2 + o) * 256 + t] * g_G[(r * 8 + i) * 64 + o * 32 + dd];
    }
    sum = warp_sum(sum);
    if (lane == 0) g_bij[r * 2 + o] += sum;
}

// ---------------- kernel: mask / argmax / output write ----------------
__global__ void mask_kernel(float* __restrict__ out) {
    int gid = blockIdx.x * blockDim.x + threadIdx.x;
    int b = gid >> 5;
    int lane = gid & 31;
    if (b >= BATCH) return;
    float v0 = g_v[b * 64 + lane];
    float v1 = g_v[b * 64 + 32 + lane];
    float n0 = warp_sum(v0 * v0);
    float n1 = warp_sum(v1 * v1);
    int idx = (n1 > n0) ? 1 : 0;
    float m0 = (idx == 0) ? 1.0f : 0.0f;
    float m1 = 1.0f - m0;
    out[OUT_V_OFF + b * 64 + lane]       = v0;
    out[OUT_V_OFF + b * 64 + 32 + lane]  = v1;
    if (lane == 0) {
        out[OUT_MASK_OFF + b * 2 + 0] = m0;
        out[OUT_MASK_OFF + b * 2 + 1] = m1;
    }
    g_h0[b * 64 + lane]      = v0 * m0;
    g_h0[b * 64 + 32 + lane] = v1 * m1;
}

// ---------------- kernel: dec3 epilogue: out = sigmoid(acc + bias) ----------------
__global__ void sigmoid_bias_kernel(const float* __restrict__ bias, float* __restrict__ out) {
    int i = blockIdx.x * blockDim.x + threadIdx.x;
    if (i >= BATCH * 64) return;
    float v = g_r[i] + bias[i & 63];
    out[OUT_REC_OFF + i] = 1.0f / (1.0f + expf(-v));
}

// ---------------- launch ----------------
extern "C" void kernel_launch(void* const* d_in, const int* in_sizes, int n_in,
                              void* d_out, int out_size)
{
    const float* data    = (const float*)d_in[0];
    const float* conv1_w = (const float*)d_in[1];
    const float* conv1_b = (const float*)d_in[2];
    const float* prim_w  = (const float*)d_in[3];
    const float* prim_b  = (const float*)d_in[4];
    const float* W_digit = (const float*)d_in[5];
    const float* dec1_w  = (const float*)d_in[6];
    const float* dec1_b  = (const float*)d_in[7];
    const float* dec2_w  = (const float*)d_in[8];
    const float* dec2_b  = (const float*)d_in[9];
    const float* dec3_w  = (const float*)d_in[10];
    const float* dec3_b  = (const float*)d_in[11];
    float* out = (float*)d_out;

    float *p_bij, *p_s, *p_G, *p_u, *p_WcT, *p_v, *p_r, *p_h0, *p_h1, *p_h2;
    cudaGetSymbolAddress((void**)&p_bij, g_bij);
    cudaGetSymbolAddress((void**)&p_s,   g_s);
    cudaGetSymbolAddress((void**)&p_G,   g_G);
    cudaGetSymbolAddress((void**)&p_u,   g_u);
    cudaGetSymbolAddress((void**)&p_WcT, g_WcT);
    cudaGetSymbolAddress((void**)&p_v,   g_v);
    cudaGetSymbolAddress((void**)&p_r,   g_r);
    cudaGetSymbolAddress((void**)&p_h0,  g_h0);
    cudaGetSymbolAddress((void**)&p_h1,  g_h1);
    cudaGetSymbolAddress((void**)&p_h2,  g_h2);

    static int smem_set = 0;
    if (!smem_set) {
        cudaFuncSetAttribute(conv_tc_kernel,
                             cudaFuncAttributeMaxDynamicSharedMemorySize, CONV_SMEM);
        smem_set = 1;
    }

    // prep (launch indices 0..4; conv_tc lands at index 5 for ncu -s 5 -c 1)
    wb_split_kernel<<<576, 256>>>(prim_w);                           // 0
    zero_kernel<<<4, 256>>>(p_bij, NR * 2);                          // 1
    zero_kernel<<<512, 256>>>(p_s, BATCH * 32);                      // 2
    zero_kernel<<<512, 256>>>(p_s + BATCH * 32, BATCH * 32);         // 3
    zero_kernel<<<1024, 256>>>(p_G, RI * 64);                        // 4

    // fused conv1 + tensor-core primary caps + squash -> g_u
    conv_tc_kernel<<<BATCH, 512, CONV_SMEM>>>(data, conv1_w, conv1_b, prim_b);  // 5

    // dynamic routing, 3 iterations
    for (int it = 0; it < 3; it++) {
        softmax_routes_kernel<<<1, 512>>>();
        build_wct_kernel<<<1024, 256>>>(W_digit);
        if (it > 0) zero_kernel<<<1024, 256>>>(p_s, BATCH * 64);
        gemm_ab_splitk_kernel<<<dim3(1, 64, 8), 256>>>(p_u, p_WcT, p_s,
                                                       BATCH, 64, RI, 512);
        squash_v_kernel<<<1024, 256>>>();
        if (it < 2) {
            if (it > 0) zero_kernel<<<1024, 256>>>(p_G, RI * 64);
            gemm_atb_splitk_kernel<<<dim3(1, 64, 8), 256>>>(p_u, p_v, p_G,
                                                            RI, 64, 512,
                                                            1.0f / (float)BATCH);
            b_update_kernel<<<128, 256>>>(W_digit);
        }
    }

    mask_kernel<<<512, 256>>>(out);
    zero_kernel<<<1024, 256>>>(p_r, BATCH * 64);

    // decoder
    gemm_ab_kernel<<<dim3(8, 64), 256>>>(p_h0, dec1_w, dec1_b, p_h1,
                                         BATCH, 512, 64, 1);
    gemm_ab_kernel<<<dim3(16, 64), 256>>>(p_h1, dec2_w, dec2_b, p_h2,
                                          BATCH, 1024, 512, 1);
    gemm_ab_splitk_kernel<<<dim3(1, 64, 4), 256>>>(p_h2, dec3_w, p_r,
                                                   BATCH, 64, 1024, 256);
    sigmoid_bias_kernel<<<1024, 256>>>(dec3_b, out);
}